// round 1
// baseline (speedup 1.0000x reference)
#include <cuda_runtime.h>
#include <math.h>
#include <stddef.h>

#define NB 4
#define NS 2048
#define NC 640
#define NH 10
#define ND 64

// Scratch (device globals — no allocations allowed)
__device__ float g_q[(size_t)NB * NH * NS * ND];   // [b][h][n][d]
__device__ float g_k[(size_t)2 * NH * NS * ND];    // [kb][h][n][d], kb = b/2 for b in {0,2}
__device__ float g_v[(size_t)2 * NH * NS * ND];
__device__ float g_o[(size_t)NB * NS * NC];        // attention output, [b][n][h*64+d]
__device__ float g_mean[NB * NH * ND];
__device__ float g_std[NB * NH * ND];

// ----------------------------------------------------------------------------
// GEMM: C = A[M,640] @ W[640,640]^T  (both row-major, K contiguous)
// MODE 0: Q   (M=8192)  -> out [b,h,n,d]
// MODE 1: K/V (M=4096, rows remapped to batches 0 and 2) -> out [kb,h,n,d]
// MODE 2: OUT (M=8192)  -> out[row,col] = acc + bias[col] + resid[row,col]
// Tiling: 128x128 block, BK=16, 256 threads, 8x8 per-thread register tile.
// ----------------------------------------------------------------------------
template <int MODE>
__global__ void __launch_bounds__(256) gemm_k(
    const float* __restrict__ A, const float* __restrict__ W,
    const float* __restrict__ bias, const float* __restrict__ resid,
    float* __restrict__ C)
{
    __shared__ float As[16][132];   // As[k][m] (transposed store, +4 pad)
    __shared__ float Bs[16][132];   // Bs[k][n]

    const int row0 = blockIdx.y * 128;
    const int col0 = blockIdx.x * 128;
    const int tid  = threadIdx.x;
    const int tr   = tid >> 4;      // 0..15
    const int tc   = tid & 15;      // 0..15

    float acc[8][8] = {};

    for (int k0 = 0; k0 < NC; k0 += 16) {
#pragma unroll
        for (int it = 0; it < 2; it++) {
            int idx = tid + it * 256;          // 0..511
            int r   = idx >> 2;                // 0..127
            int c4  = (idx & 3) * 4;           // 0,4,8,12
            int lr  = row0 + r;
            int arow = (MODE == 1) ? ((lr & 2047) + ((lr >> 11) << 12)) : lr;
            float4 va = *(const float4*)(A + (size_t)arow * NC + k0 + c4);
            As[c4 + 0][r] = va.x; As[c4 + 1][r] = va.y;
            As[c4 + 2][r] = va.z; As[c4 + 3][r] = va.w;
            float4 vb = *(const float4*)(W + (size_t)(col0 + r) * NC + k0 + c4);
            Bs[c4 + 0][r] = vb.x; Bs[c4 + 1][r] = vb.y;
            Bs[c4 + 2][r] = vb.z; Bs[c4 + 3][r] = vb.w;
        }
        __syncthreads();

#pragma unroll
        for (int kk = 0; kk < 16; kk++) {
            float a[8], bb[8];
            float4 a0 = *(const float4*)&As[kk][tr * 8];
            float4 a1 = *(const float4*)&As[kk][tr * 8 + 4];
            a[0]=a0.x; a[1]=a0.y; a[2]=a0.z; a[3]=a0.w;
            a[4]=a1.x; a[5]=a1.y; a[6]=a1.z; a[7]=a1.w;
            float4 b0 = *(const float4*)&Bs[kk][tc * 8];
            float4 b1 = *(const float4*)&Bs[kk][tc * 8 + 4];
            bb[0]=b0.x; bb[1]=b0.y; bb[2]=b0.z; bb[3]=b0.w;
            bb[4]=b1.x; bb[5]=b1.y; bb[6]=b1.z; bb[7]=b1.w;
#pragma unroll
            for (int i = 0; i < 8; i++)
#pragma unroll
                for (int j = 0; j < 8; j++)
                    acc[i][j] += a[i] * bb[j];
        }
        __syncthreads();
    }

    // Epilogue
#pragma unroll
    for (int i = 0; i < 8; i++) {
        int r = row0 + tr * 8 + i;
#pragma unroll
        for (int j = 0; j < 8; j++) {
            int cgl = col0 + tc * 8 + j;
            float v = acc[i][j];
            if (MODE == 2) {
                C[(size_t)r * NC + cgl] = v + bias[cgl] + resid[(size_t)r * NC + cgl];
            } else {
                int bb_ = r >> 11;       // batch (or kb for MODE 1)
                int n   = r & 2047;
                int h   = cgl >> 6;
                int d   = cgl & 63;
                C[(((size_t)(bb_ * NH + h)) * NS + n) * ND + d] = v;
            }
        }
    }
}

// ----------------------------------------------------------------------------
// AdaIN stats: mean/std over n per (b,h,d), ddof=1, std = sqrt(var + 1e-5)
// One block per (b,h), 256 threads = 64 d-cols x 4 partial groups.
// ----------------------------------------------------------------------------
__global__ void __launch_bounds__(256) adain_stats(
    const float* __restrict__ q, float* __restrict__ mn, float* __restrict__ sd)
{
    int bh = blockIdx.x;                       // 0..39
    const float* base = q + (size_t)bh * NS * ND;
    int d = threadIdx.x & 63;
    int part = threadIdx.x >> 6;               // 0..3
    float s = 0.f, ss = 0.f;
    for (int n = part; n < NS; n += 4) {
        float x = base[(size_t)n * ND + d];
        s += x; ss += x * x;
    }
    __shared__ float sh_s[4][64];
    __shared__ float sh_q[4][64];
    sh_s[part][d] = s; sh_q[part][d] = ss;
    __syncthreads();
    if (threadIdx.x < 64) {
        int dd = threadIdx.x;
        float S  = sh_s[0][dd] + sh_s[1][dd] + sh_s[2][dd] + sh_s[3][dd];
        float Q2 = sh_q[0][dd] + sh_q[1][dd] + sh_q[2][dd] + sh_q[3][dd];
        float m   = S / (float)NS;
        float var = (Q2 - S * m) / (float)(NS - 1);
        mn[bh * ND + dd] = m;
        sd[bh * ND + dd] = sqrtf(var + 1e-5f);
    }
}

// ----------------------------------------------------------------------------
// AdaIN apply: batches 1 and 3 only: x -> (x - m_own) * (s_src/s_own) + m_src
// ----------------------------------------------------------------------------
__global__ void __launch_bounds__(256) adain_apply(
    float* __restrict__ q, const float* __restrict__ mn, const float* __restrict__ sd)
{
    int i = blockIdx.x * 256 + threadIdx.x;    // 0 .. 2*10*2048*64-1
    int d = i & 63;
    int n = (i >> 6) & 2047;
    int rest = i >> 17;                        // 0..19
    int h  = rest % NH;
    int bi = rest / NH;                        // 0 or 1
    int b   = bi * 2 + 1;
    int src = bi * 2;
    int so = (b   * NH + h) * ND + d;
    int sr = (src * NH + h) * ND + d;
    size_t qi = (((size_t)(b * NH + h)) * NS + n) * ND + d;
    float x = q[qi];
    q[qi] = (x - mn[so]) * (sd[sr] / sd[so]) + mn[sr];
}

// ----------------------------------------------------------------------------
// Flash attention, fp32. Grid (32 q-tiles, 40 bh). 256 threads.
// BQ = BK = 64, D = 64. Per thread: 4x4 S tile + 4x4 O tile (rows ty*4.., cols tx*4..).
// Online softmax; row groups = 16 lanes (shuffle reductions).
// ----------------------------------------------------------------------------
#define SAST 65   // smem row stride (pad)

__global__ void __launch_bounds__(256) attn_k(
    const float* __restrict__ q, const float* __restrict__ k,
    const float* __restrict__ v, float* __restrict__ o)
{
    extern __shared__ float sm[];
    float* sQ = sm;                   // 64 x 65
    float* sK = sm + 64 * SAST;
    float* sV = sm + 2 * 64 * SAST;
    float* sP = sm + 3 * 64 * SAST;

    const int bh = blockIdx.y;
    const int b  = bh / NH;
    const int h  = bh % NH;
    const int kb = b >> 1;
    const float* Qg = q + (size_t)bh * NS * ND + (size_t)blockIdx.x * 64 * ND;
    const float* Kg = k + (size_t)(kb * NH + h) * NS * ND;
    const float* Vg = v + (size_t)(kb * NH + h) * NS * ND;

    const int tid = threadIdx.x;
    const int ty  = tid >> 4;         // 0..15 -> rows ty*4..ty*4+3
    const int tx  = tid & 15;         // 0..15 -> cols tx*4..tx*4+3

    // Load Q tile (pre-scaled by attn scale)
#pragma unroll
    for (int it = 0; it < 4; it++) {
        int idx = tid + it * 256;     // 0..1023
        int r  = idx >> 4;
        int c4 = (idx & 15) * 4;
        float4 va = *(const float4*)(Qg + (size_t)r * ND + c4);
        sQ[r * SAST + c4 + 0] = va.x * 0.125f;
        sQ[r * SAST + c4 + 1] = va.y * 0.125f;
        sQ[r * SAST + c4 + 2] = va.z * 0.125f;
        sQ[r * SAST + c4 + 3] = va.w * 0.125f;
    }

    float m[4], l[4], acc[4][4];
#pragma unroll
    for (int i = 0; i < 4; i++) {
        m[i] = -1e30f; l[i] = 0.f;
#pragma unroll
        for (int j = 0; j < 4; j++) acc[i][j] = 0.f;
    }

    for (int kt = 0; kt < NS / 64; kt++) {
        __syncthreads();   // previous tile's PV reads done before overwrite
#pragma unroll
        for (int it = 0; it < 4; it++) {
            int idx = tid + it * 256;
            int r  = idx >> 4;
            int c4 = (idx & 15) * 4;
            size_t goff = (size_t)kt * 64 * ND + (size_t)r * ND + c4;
            float4 vk = *(const float4*)(Kg + goff);
            sK[r * SAST + c4 + 0] = vk.x; sK[r * SAST + c4 + 1] = vk.y;
            sK[r * SAST + c4 + 2] = vk.z; sK[r * SAST + c4 + 3] = vk.w;
            float4 vv = *(const float4*)(Vg + goff);
            sV[r * SAST + c4 + 0] = vv.x; sV[r * SAST + c4 + 1] = vv.y;
            sV[r * SAST + c4 + 2] = vv.z; sV[r * SAST + c4 + 3] = vv.w;
        }
        __syncthreads();

        // S = (Q*scale) @ K^T  (4x4 per thread)
        float s[4][4] = {};
#pragma unroll 16
        for (int kk = 0; kk < 64; kk++) {
            float a0 = sQ[(ty * 4 + 0) * SAST + kk];
            float a1 = sQ[(ty * 4 + 1) * SAST + kk];
            float a2 = sQ[(ty * 4 + 2) * SAST + kk];
            float a3 = sQ[(ty * 4 + 3) * SAST + kk];
            float b0 = sK[(tx * 4 + 0) * SAST + kk];
            float b1 = sK[(tx * 4 + 1) * SAST + kk];
            float b2 = sK[(tx * 4 + 2) * SAST + kk];
            float b3 = sK[(tx * 4 + 3) * SAST + kk];
            s[0][0] += a0*b0; s[0][1] += a0*b1; s[0][2] += a0*b2; s[0][3] += a0*b3;
            s[1][0] += a1*b0; s[1][1] += a1*b1; s[1][2] += a1*b2; s[1][3] += a1*b3;
            s[2][0] += a2*b0; s[2][1] += a2*b1; s[2][2] += a2*b2; s[2][3] += a2*b3;
            s[3][0] += a3*b0; s[3][1] += a3*b1; s[3][2] += a3*b2; s[3][3] += a3*b3;
        }

        // Online softmax (row groups of 16 lanes; shuffle xor stays in-group)
#pragma unroll
        for (int i = 0; i < 4; i++) {
            float rmax = fmaxf(fmaxf(s[i][0], s[i][1]), fmaxf(s[i][2], s[i][3]));
#pragma unroll
            for (int off = 1; off < 16; off <<= 1)
                rmax = fmaxf(rmax, __shfl_xor_sync(0xffffffffu, rmax, off));
            float nm = fmaxf(m[i], rmax);
            float al = __expf(m[i] - nm);
            s[i][0] = __expf(s[i][0] - nm);
            s[i][1] = __expf(s[i][1] - nm);
            s[i][2] = __expf(s[i][2] - nm);
            s[i][3] = __expf(s[i][3] - nm);
            float rs = s[i][0] + s[i][1] + s[i][2] + s[i][3];
#pragma unroll
            for (int off = 1; off < 16; off <<= 1)
                rs += __shfl_xor_sync(0xffffffffu, rs, off);
            l[i] = l[i] * al + rs;
            m[i] = nm;
            acc[i][0] *= al; acc[i][1] *= al; acc[i][2] *= al; acc[i][3] *= al;
            // write P row chunk
            sP[(ty * 4 + i) * SAST + tx * 4 + 0] = s[i][0];
            sP[(ty * 4 + i) * SAST + tx * 4 + 1] = s[i][1];
            sP[(ty * 4 + i) * SAST + tx * 4 + 2] = s[i][2];
            sP[(ty * 4 + i) * SAST + tx * 4 + 3] = s[i][3];
        }
        __syncthreads();

        // O += P @ V  (4x4 per thread)
#pragma unroll 16
        for (int jj = 0; jj < 64; jj++) {
            float p0 = sP[(ty * 4 + 0) * SAST + jj];
            float p1 = sP[(ty * 4 + 1) * SAST + jj];
            float p2 = sP[(ty * 4 + 2) * SAST + jj];
            float p3 = sP[(ty * 4 + 3) * SAST + jj];
            float v0 = sV[jj * SAST + tx * 4 + 0];
            float v1 = sV[jj * SAST + tx * 4 + 1];
            float v2 = sV[jj * SAST + tx * 4 + 2];
            float v3 = sV[jj * SAST + tx * 4 + 3];
            acc[0][0] += p0*v0; acc[0][1] += p0*v1; acc[0][2] += p0*v2; acc[0][3] += p0*v3;
            acc[1][0] += p1*v0; acc[1][1] += p1*v1; acc[1][2] += p1*v2; acc[1][3] += p1*v3;
            acc[2][0] += p2*v0; acc[2][1] += p2*v1; acc[2][2] += p2*v2; acc[2][3] += p2*v3;
            acc[3][0] += p3*v0; acc[3][1] += p3*v1; acc[3][2] += p3*v2; acc[3][3] += p3*v3;
        }
    }

    // Epilogue: o[b][n][h*64+d] = acc / l
    const int n0 = blockIdx.x * 64;
#pragma unroll
    for (int i = 0; i < 4; i++) {
        float inv = 1.f / l[i];
        int r = n0 + ty * 4 + i;
        size_t rowbase = ((size_t)b * NS + r) * NC + h * ND;
#pragma unroll
        for (int j = 0; j < 4; j++)
            o[rowbase + tx * 4 + j] = acc[i][j] * inv;
    }
}

// ----------------------------------------------------------------------------
extern "C" void kernel_launch(void* const* d_in, const int* in_sizes, int n_in,
                              void* d_out, int out_size)
{
    const float* hs = (const float*)d_in[0];
    const float* wq = (const float*)d_in[1];
    const float* wk = (const float*)d_in[2];
    const float* wv = (const float*)d_in[3];
    const float* wo = (const float*)d_in[4];
    const float* bo = (const float*)d_in[5];
    float* out = (float*)d_out;

    float *q, *k, *v, *o, *mn, *sd;
    cudaGetSymbolAddress((void**)&q,  g_q);
    cudaGetSymbolAddress((void**)&k,  g_k);
    cudaGetSymbolAddress((void**)&v,  g_v);
    cudaGetSymbolAddress((void**)&o,  g_o);
    cudaGetSymbolAddress((void**)&mn, g_mean);
    cudaGetSymbolAddress((void**)&sd, g_std);

    const int attn_smem = 4 * 64 * SAST * (int)sizeof(float);   // 66560 B
    cudaFuncSetAttribute(attn_k, cudaFuncAttributeMaxDynamicSharedMemorySize, attn_smem);

    // QKV projections (K/V only for batches 0 and 2)
    gemm_k<0><<<dim3(5, 64), 256>>>(hs, wq, nullptr, nullptr, q);
    gemm_k<1><<<dim3(5, 32), 256>>>(hs, wk, nullptr, nullptr, k);
    gemm_k<1><<<dim3(5, 32), 256>>>(hs, wv, nullptr, nullptr, v);

    // AdaIN on Q (stats for all batches, transform batches 1,3 only)
    adain_stats<<<40, 256>>>(q, mn, sd);
    adain_apply<<<(2 * NH * NS * ND) / 256, 256>>>(q, mn, sd);

    // Attention (K/V read from source batch b>>1)
    attn_k<<<dim3(NS / 64, NB * NH), 256, attn_smem>>>(q, k, v, o);

    // Output projection + bias + residual
    gemm_k<2><<<dim3(5, 64), 256>>>(o, wo, bo, hs, out);
}

// round 3
// speedup vs baseline: 5.8387x; 5.8387x over previous
#include <cuda_runtime.h>
#include <cuda_bf16.h>
#include <math.h>
#include <stddef.h>
#include <stdint.h>

#define NB 4
#define NS 2048
#define NC 640
#define NH 10
#define ND 64

// ---------------- device scratch (no allocs allowed) ----------------
__device__ __nv_bfloat16 g_hsb[(size_t)NB * NS * NC];     // hs bf16
__device__ __nv_bfloat16 g_wqb[NC * NC];
__device__ __nv_bfloat16 g_wkb[NC * NC];
__device__ __nv_bfloat16 g_wvb[NC * NC];
__device__ __nv_bfloat16 g_wob[NC * NC];
__device__ float         g_qf [(size_t)NB * NS * NC];     // q fp32 (pre-adain)
__device__ __nv_bfloat16 g_qb [(size_t)NB * NS * NC];     // q bf16 (post-adain, *0.125)
__device__ __nv_bfloat16 g_kb [(size_t)2  * NS * NC];     // k bf16 (batches 0,2)
__device__ __nv_bfloat16 g_vb [(size_t)2  * NS * NC];
__device__ __nv_bfloat16 g_ob [(size_t)NB * NS * NC];     // attention out bf16
__device__ float g_mn[NB * NC];
__device__ float g_sd[NB * NC];

// ---------------- PTX helpers (all baseline sm_80+, safe on sm_100) --------
__device__ __forceinline__ uint32_t smem_u32(const void* p) {
    uint32_t a;
    asm("{ .reg .u64 t; cvta.to.shared.u64 t, %1; cvt.u32.u64 %0, t; }" : "=r"(a) : "l"(p));
    return a;
}

#define CP16(dst, src) \
    asm volatile("cp.async.cg.shared.global [%0], [%1], 16;" :: "r"(dst), "l"(src))
#define CP_COMMIT() asm volatile("cp.async.commit_group;" ::: "memory")
#define CP_WAIT1()  asm volatile("cp.async.wait_group 1;" ::: "memory")

__device__ __forceinline__ void ldm_x4(uint32_t& r0, uint32_t& r1, uint32_t& r2, uint32_t& r3, uint32_t a) {
    asm volatile("ldmatrix.sync.aligned.m8n8.x4.shared.b16 {%0,%1,%2,%3}, [%4];"
        : "=r"(r0), "=r"(r1), "=r"(r2), "=r"(r3) : "r"(a));
}
__device__ __forceinline__ void ldm_x2(uint32_t& r0, uint32_t& r1, uint32_t a) {
    asm volatile("ldmatrix.sync.aligned.m8n8.x2.shared.b16 {%0,%1}, [%2];"
        : "=r"(r0), "=r"(r1) : "r"(a));
}
__device__ __forceinline__ void ldm_x2t(uint32_t& r0, uint32_t& r1, uint32_t a) {
    asm volatile("ldmatrix.sync.aligned.m8n8.x2.trans.shared.b16 {%0,%1}, [%2];"
        : "=r"(r0), "=r"(r1) : "r"(a));
}
__device__ __forceinline__ void mma_bf16(float* c, uint32_t a0, uint32_t a1, uint32_t a2, uint32_t a3,
                                         uint32_t b0, uint32_t b1) {
    asm volatile("mma.sync.aligned.m16n8k16.row.col.f32.bf16.bf16.f32 "
        "{%0,%1,%2,%3}, {%4,%5,%6,%7}, {%8,%9}, {%0,%1,%2,%3};"
        : "+f"(c[0]), "+f"(c[1]), "+f"(c[2]), "+f"(c[3])
        : "r"(a0), "r"(a1), "r"(a2), "r"(a3), "r"(b0), "r"(b1));
}
__device__ __forceinline__ uint32_t packbf(float lo, float hi) {
    __nv_bfloat162 p = __floats2bfloat162_rn(lo, hi);
    return *(uint32_t*)&p;
}

// ---------------- convert kernels ----------------
__global__ void __launch_bounds__(256) convk(const float* __restrict__ in,
                                             __nv_bfloat16* __restrict__ out, int n4) {
    int i = blockIdx.x * 256 + threadIdx.x;
    if (i < n4) {
        float4 v = ((const float4*)in)[i];
        uint2 o;
        o.x = packbf(v.x, v.y);
        o.y = packbf(v.z, v.w);
        ((uint2*)out)[i] = o;
    }
}

// ---------------- GEMM: C[M,640] = A[M,640] @ W[640,640]^T ------------------
// MODE 0: out fp32 (Q). MODE 1: input rows remapped to batches {0,2}, out bf16
// (K/V). MODE 2: fp32 out + bias + residual (final projection).
// 128x128 block, BK=32, 256 threads (8 warps, each 32x64), cp.async 2-stage.
// smem rows padded to 80B -> conflict-free ldmatrix.
template <int MODE>
__global__ void __launch_bounds__(256) gemm_mma(
    const __nv_bfloat16* __restrict__ A, const __nv_bfloat16* __restrict__ W,
    const float* __restrict__ bias, const float* __restrict__ resid,
    float* __restrict__ outF, __nv_bfloat16* __restrict__ outB)
{
    __shared__ __align__(16) char smem[40960];   // 2 stages x (A 10240 + B 10240)
    const uint32_t sb = smem_u32(smem);
    const int tid = threadIdx.x;
    const int w = tid >> 5, lam = tid & 31;
    const int row0 = blockIdx.y * 128, col0 = blockIdx.x * 128;
    const int warp_m = (w & 3) * 32, warp_n = (w >> 2) * 64;

    // loader mapping: thread -> (row tid/2, 32B half tid&1)
    const int lrow = tid >> 1;
    const int gr = row0 + lrow;
    const int arow = (MODE == 1) ? ((gr & 2047) + ((gr >> 11) << 12)) : gr;
    const char* ag = (const char*)(A + (size_t)arow * NC) + (tid & 1) * 32;
    const char* bg = (const char*)(W + (size_t)(col0 + lrow) * NC) + (tid & 1) * 32;
    const uint32_t asb = sb + lrow * 80 + (tid & 1) * 32;
    const uint32_t bsb = sb + 10240 + lrow * 80 + (tid & 1) * 32;

    float acc[2][8][4];
#pragma unroll
    for (int i = 0; i < 2; i++)
#pragma unroll
        for (int j = 0; j < 8; j++)
#pragma unroll
            for (int e = 0; e < 4; e++) acc[i][j][e] = 0.f;

    // prologue: stages 0,1 (k-chunks 0,1); chunk c covers bytes c*64..c*64+63
#pragma unroll
    for (int s = 0; s < 2; s++) {
        uint32_t so = s * 20480;
        int kb_ = s * 64;
        CP16(asb + so, ag + kb_); CP16(asb + so + 16, ag + kb_ + 16);
        CP16(bsb + so, bg + kb_); CP16(bsb + so + 16, bg + kb_ + 16);
        CP_COMMIT();
    }

    for (int c = 0; c < 20; c++) {
        CP_WAIT1(); __syncthreads();
        const int st = c & 1;
        const uint32_t sa  = sb + st * 20480;
        const uint32_t sbm = sb + 10240 + st * 20480;
        const uint32_t aab = sa + (warp_m + (lam & 15)) * 80 + (lam >> 4) * 16;
        const uint32_t bab = sbm + (warp_n + (lam & 7)) * 80 + ((lam >> 3) & 1) * 16;
#pragma unroll
        for (int s = 0; s < 2; s++) {
            uint32_t a0[4], a1[4];
            ldm_x4(a0[0], a0[1], a0[2], a0[3], aab + s * 32);
            ldm_x4(a1[0], a1[1], a1[2], a1[3], aab + 16 * 80 + s * 32);
#pragma unroll
            for (int j = 0; j < 8; j++) {
                uint32_t b0, b1;
                ldm_x2(b0, b1, bab + j * (8 * 80) + s * 32);
                mma_bf16(acc[0][j], a0[0], a0[1], a0[2], a0[3], b0, b1);
                mma_bf16(acc[1][j], a1[0], a1[1], a1[2], a1[3], b0, b1);
            }
        }
        __syncthreads();
        if (c + 2 < 20) {
            uint32_t so = st * 20480;
            int kb_ = (c + 2) * 64;
            CP16(asb + so, ag + kb_); CP16(asb + so + 16, ag + kb_ + 16);
            CP16(bsb + so, bg + kb_); CP16(bsb + so + 16, bg + kb_ + 16);
        }
        CP_COMMIT();
    }

    // epilogue: c-frag (row lam/4 (+8), col 2*(lam&3) (+1))
    const int rb = row0 + warp_m + (lam >> 2);
    const int cb = col0 + warp_n + 2 * (lam & 3);
#pragma unroll
    for (int im = 0; im < 2; im++) {
#pragma unroll
        for (int j = 0; j < 8; j++) {
            int r = rb + im * 16;
            int cc = cb + j * 8;
            float* a4 = acc[im][j];
            if (MODE == 2) {
                size_t o0 = (size_t)r * NC + cc;
                size_t o1 = (size_t)(r + 8) * NC + cc;
                float2 rv0 = *(const float2*)(resid + o0);
                float2 rv1 = *(const float2*)(resid + o1);
                float2 bv = *(const float2*)(bias + cc);
                *(float2*)(outF + o0) = make_float2(a4[0] + bv.x + rv0.x, a4[1] + bv.y + rv0.y);
                *(float2*)(outF + o1) = make_float2(a4[2] + bv.x + rv1.x, a4[3] + bv.y + rv1.y);
            } else if (MODE == 0) {
                *(float2*)(outF + (size_t)r * NC + cc) = make_float2(a4[0], a4[1]);
                *(float2*)(outF + (size_t)(r + 8) * NC + cc) = make_float2(a4[2], a4[3]);
            } else {
                *(uint32_t*)(outB + (size_t)r * NC + cc) = packbf(a4[0], a4[1]);
                *(uint32_t*)(outB + (size_t)(r + 8) * NC + cc) = packbf(a4[2], a4[3]);
            }
        }
    }
}

// ---------------- AdaIN stats (over n, per (b, col)), ddof=1 ----------------
__global__ void __launch_bounds__(256) adain_stats2(
    const float* __restrict__ qf, float* __restrict__ mn, float* __restrict__ sd)
{
    int b  = blockIdx.x / 10;
    int cg = blockIdx.x % 10;
    int c  = cg * 64 + (threadIdx.x & 63);
    int part = threadIdx.x >> 6;
    const float* base = qf + (size_t)b * NS * NC + c;
    float s = 0.f, ss = 0.f;
    for (int n = part; n < NS; n += 4) {
        float x = base[(size_t)n * NC];
        s += x; ss += x * x;
    }
    __shared__ float sh_s[4][64], sh_q[4][64];
    sh_s[part][threadIdx.x & 63] = s;
    sh_q[part][threadIdx.x & 63] = ss;
    __syncthreads();
    if (threadIdx.x < 64) {
        int d = threadIdx.x;
        float S  = sh_s[0][d] + sh_s[1][d] + sh_s[2][d] + sh_s[3][d];
        float Q2 = sh_q[0][d] + sh_q[1][d] + sh_q[2][d] + sh_q[3][d];
        float m   = S / (float)NS;
        float var = (Q2 - S * m) / (float)(NS - 1);
        mn[b * NC + cg * 64 + d] = m;
        sd[b * NC + cg * 64 + d] = sqrtf(var + 1e-5f);
    }
}

// ---------------- AdaIN apply (odd batches) + convert to bf16 (*0.125) ------
__global__ void __launch_bounds__(160) adain_conv(
    const float* __restrict__ qf, const float* __restrict__ mn,
    const float* __restrict__ sd, __nv_bfloat16* __restrict__ qb)
{
    int row = blockIdx.x;               // 0..8191
    int b = row >> 11;
    int c = threadIdx.x * 4;
    float4 x = *(const float4*)(qf + (size_t)row * NC + c);
    if (b & 1) {
        int src = b - 1;
        float4 mo = *(const float4*)(mn + b * NC + c);
        float4 so = *(const float4*)(sd + b * NC + c);
        float4 ms = *(const float4*)(mn + src * NC + c);
        float4 ssr = *(const float4*)(sd + src * NC + c);
        x.x = (x.x - mo.x) * (ssr.x / so.x) + ms.x;
        x.y = (x.y - mo.y) * (ssr.y / so.y) + ms.y;
        x.z = (x.z - mo.z) * (ssr.z / so.z) + ms.z;
        x.w = (x.w - mo.w) * (ssr.w / so.w) + ms.w;
    }
    uint2 o;
    o.x = packbf(x.x * 0.125f, x.y * 0.125f);
    o.y = packbf(x.z * 0.125f, x.w * 0.125f);
    *(uint2*)(qb + (size_t)row * NC + c) = o;
}

// ---------------- Flash attention via mma.sync ------------------------------
// Block: 128 q-rows of one (b,h), 256 threads (8 warps x 16 rows). BK=64.
// cp.async 2-stage KV pipeline. No-max softmax (logits bounded ~|4|):
// O accumulates in registers across the full KV loop, one divide at the end.
__global__ void __launch_bounds__(256) attn_mma(
    const __nv_bfloat16* __restrict__ q, const __nv_bfloat16* __restrict__ k,
    const __nv_bfloat16* __restrict__ v, __nv_bfloat16* __restrict__ o)
{
    extern __shared__ __align__(16) char smd[];
    // layout: Q 128x144B @0 (18432); stage s: K @18432+s*18432.. wait —
    // K(s) @ 18432 + s*18432*? -> offsets: K0 18432, V0 27648, K1 36864, V1 46080
    const uint32_t sb = smem_u32(smd);
    const int tid = threadIdx.x, w = tid >> 5, lam = tid & 31;
    const int by = blockIdx.y;
    const int b = by / NH, h = by % NH, kb = b >> 1;
    const int q0 = blockIdx.x * 128;

    const char* qg = (const char*)(q + ((size_t)b * NS + q0 + (tid >> 1)) * NC + h * 64) + (tid & 1) * 64;
    const char* kg = (const char*)(k + ((size_t)kb * NS + (tid >> 2)) * NC + h * 64) + (tid & 3) * 32;
    const char* vg = (const char*)(v + ((size_t)kb * NS + (tid >> 2)) * NC + h * 64) + (tid & 3) * 32;
    const uint32_t qs  = sb + (tid >> 1) * 144 + (tid & 1) * 64;
    const uint32_t ksb = sb + 18432 + (tid >> 2) * 144 + (tid & 3) * 32;
    const uint32_t vsb = sb + 27648 + (tid >> 2) * 144 + (tid & 3) * 32;
    const size_t kv_step = (size_t)64 * NC * 2;   // bytes per 64-row kv tile

    // prologue: Q + KV tile0 (group 0), KV tile1 (group 1)
#pragma unroll
    for (int i = 0; i < 4; i++) CP16(qs + i * 16, qg + i * 16);
    CP16(ksb, kg); CP16(ksb + 16, kg + 16);
    CP16(vsb, vg); CP16(vsb + 16, vg + 16);
    CP_COMMIT();
    CP16(ksb + 18432, kg + kv_step); CP16(ksb + 18432 + 16, kg + kv_step + 16);
    CP16(vsb + 18432, vg + kv_step); CP16(vsb + 18432 + 16, vg + kv_step + 16);
    CP_COMMIT();
    CP_WAIT1(); __syncthreads();

    // preload Q fragments (warp's 16 rows, 4 k16 steps)
    uint32_t aq[4][4];
    {
        uint32_t qab = sb + (w * 16 + (lam & 15)) * 144 + (lam >> 4) * 16;
#pragma unroll
        for (int t = 0; t < 4; t++)
            ldm_x4(aq[t][0], aq[t][1], aq[t][2], aq[t][3], qab + t * 32);
    }

    float oacc[8][4];
#pragma unroll
    for (int j = 0; j < 8; j++)
#pragma unroll
        for (int e = 0; e < 4; e++) oacc[j][e] = 0.f;
    float l0 = 0.f, l1 = 0.f;

    const uint32_t kab0 = sb + 18432 + (lam & 7) * 144 + ((lam >> 3) & 1) * 16;
    const uint32_t vab0 = sb + 27648 + (lam & 15) * 144;

    for (int i = 0; i < 32; i++) {
        const int st = i & 1;
        const uint32_t kab = kab0 + st * 18432;
        const uint32_t vab = vab0 + st * 18432;

        // S = Q @ K^T : c[j] covers kv cols 8j..8j+7
        float c[8][4];
#pragma unroll
        for (int j = 0; j < 8; j++)
#pragma unroll
            for (int e = 0; e < 4; e++) c[j][e] = 0.f;
#pragma unroll
        for (int t = 0; t < 4; t++) {
#pragma unroll
            for (int j = 0; j < 8; j++) {
                uint32_t b0, b1;
                ldm_x2(b0, b1, kab + j * (8 * 144) + t * 32);
                mma_bf16(c[j], aq[t][0], aq[t][1], aq[t][2], aq[t][3], b0, b1);
            }
        }
        // exp (no max subtraction) + row-sum partials
        float p0 = 0.f, p1 = 0.f;
#pragma unroll
        for (int j = 0; j < 8; j++) {
            c[j][0] = __expf(c[j][0]); c[j][1] = __expf(c[j][1]);
            c[j][2] = __expf(c[j][2]); c[j][3] = __expf(c[j][3]);
            p0 += c[j][0] + c[j][1];
            p1 += c[j][2] + c[j][3];
        }
        l0 += p0; l1 += p1;
        // repack C-frags (m16n8 pairs) as A-frags (m16k16) for P@V
        uint32_t ap[4][4];
#pragma unroll
        for (int t = 0; t < 4; t++) {
            ap[t][0] = packbf(c[2*t][0],     c[2*t][1]);
            ap[t][1] = packbf(c[2*t][2],     c[2*t][3]);
            ap[t][2] = packbf(c[2*t+1][0],   c[2*t+1][1]);
            ap[t][3] = packbf(c[2*t+1][2],   c[2*t+1][3]);
        }
        // O += P @ V  (V loaded transposed: kv-major rows -> B k16n8 frags)
#pragma unroll
        for (int t = 0; t < 4; t++) {
#pragma unroll
            for (int j = 0; j < 8; j++) {
                uint32_t b0, b1;
                ldm_x2t(b0, b1, vab + t * (16 * 144) + j * 16);
                mma_bf16(oacc[j], ap[t][0], ap[t][1], ap[t][2], ap[t][3], b0, b1);
            }
        }
        __syncthreads();
        if (i + 2 < 32) {
            const char* kgi = kg + (size_t)(i + 2) * kv_step;
            const char* vgi = vg + (size_t)(i + 2) * kv_step;
            uint32_t ko = ksb + st * 18432, vo = vsb + st * 18432;
            CP16(ko, kgi); CP16(ko + 16, kgi + 16);
            CP16(vo, vgi); CP16(vo + 16, vgi + 16);
        }
        CP_COMMIT();
        CP_WAIT1(); __syncthreads();
    }

    // finalize: reduce row-sums across the 4 lanes sharing each row
    l0 += __shfl_xor_sync(0xffffffffu, l0, 1);
    l0 += __shfl_xor_sync(0xffffffffu, l0, 2);
    l1 += __shfl_xor_sync(0xffffffffu, l1, 1);
    l1 += __shfl_xor_sync(0xffffffffu, l1, 2);
    const float i0 = 1.f / l0, i1 = 1.f / l1;

    const int r = q0 + w * 16 + (lam >> 2);
    __nv_bfloat16* ob0 = o + ((size_t)b * NS + r) * NC + h * 64 + 2 * (lam & 3);
#pragma unroll
    for (int j = 0; j < 8; j++) {
        *(uint32_t*)(ob0 + j * 8)          = packbf(oacc[j][0] * i0, oacc[j][1] * i0);
        *(uint32_t*)(ob0 + 8 * NC + j * 8) = packbf(oacc[j][2] * i1, oacc[j][3] * i1);
    }
}

// ---------------- launch ----------------
extern "C" void kernel_launch(void* const* d_in, const int* in_sizes, int n_in,
                              void* d_out, int out_size)
{
    const float* hs = (const float*)d_in[0];
    const float* wq = (const float*)d_in[1];
    const float* wk = (const float*)d_in[2];
    const float* wv = (const float*)d_in[3];
    const float* wo = (const float*)d_in[4];
    const float* bo = (const float*)d_in[5];
    float* out = (float*)d_out;

    __nv_bfloat16 *hsb, *wqb, *wkb, *wvb, *wob, *qb, *kbp, *vbp, *obp;
    float *qf, *mn, *sd;
    cudaGetSymbolAddress((void**)&hsb, g_hsb);
    cudaGetSymbolAddress((void**)&wqb, g_wqb);
    cudaGetSymbolAddress((void**)&wkb, g_wkb);
    cudaGetSymbolAddress((void**)&wvb, g_wvb);
    cudaGetSymbolAddress((void**)&wob, g_wob);
    cudaGetSymbolAddress((void**)&qf,  g_qf);
    cudaGetSymbolAddress((void**)&qb,  g_qb);
    cudaGetSymbolAddress((void**)&kbp, g_kb);
    cudaGetSymbolAddress((void**)&vbp, g_vb);
    cudaGetSymbolAddress((void**)&obp, g_ob);
    cudaGetSymbolAddress((void**)&mn,  g_mn);
    cudaGetSymbolAddress((void**)&sd,  g_sd);

    const int ATTN_SMEM = 55296;
    cudaFuncSetAttribute(attn_mma, cudaFuncAttributeMaxDynamicSharedMemorySize, ATTN_SMEM);

    // fp32 -> bf16 converts
    convk<<<5120, 256>>>(hs, hsb, (NB * NS * NC) / 4);
    convk<<<400, 256>>>(wq, wqb, (NC * NC) / 4);
    convk<<<400, 256>>>(wk, wkb, (NC * NC) / 4);
    convk<<<400, 256>>>(wv, wvb, (NC * NC) / 4);
    convk<<<400, 256>>>(wo, wob, (NC * NC) / 4);

    // projections (K/V only for source batches 0,2)
    gemm_mma<0><<<dim3(5, 64), 256>>>(hsb, wqb, nullptr, nullptr, qf, nullptr);
    gemm_mma<1><<<dim3(5, 32), 256>>>(hsb, wkb, nullptr, nullptr, nullptr, kbp);
    gemm_mma<1><<<dim3(5, 32), 256>>>(hsb, wvb, nullptr, nullptr, nullptr, vbp);

    // AdaIN on Q (stats all batches; transform odd batches), fused *0.125 + bf16
    adain_stats2<<<40, 256>>>(qf, mn, sd);
    adain_conv<<<NB * NS, 160>>>(qf, mn, sd, qb);

    // attention
    attn_mma<<<dim3(16, 40), 256, ATTN_SMEM>>>(qb, kbp, vbp, obp);

    // output projection + bias + residual (fp32)
    gemm_mma<2><<<dim3(5, 64), 256>>>(obp, wob, bo, hs, out, nullptr);
}

// round 4
// speedup vs baseline: 6.7436x; 1.1550x over previous
#include <cuda_runtime.h>
#include <cuda_bf16.h>
#include <math.h>
#include <stddef.h>
#include <stdint.h>

#define NB 4
#define NS 2048
#define NC 640
#define NH 10
#define ND 64

// log2(e) * attn_scale(0.125): applied to q AFTER adain; softmax uses ex2
#define QSCALE 0.1803368801111204f

// ---------------- device scratch (no allocs allowed) ----------------
__device__ __nv_bfloat16 g_hsb[(size_t)NB * NS * NC];
__device__ __nv_bfloat16 g_wqb[NC * NC];
__device__ __nv_bfloat16 g_wkb[NC * NC];
__device__ __nv_bfloat16 g_wvb[NC * NC];
__device__ __nv_bfloat16 g_wob[NC * NC];
__device__ __nv_bfloat16 g_qb [(size_t)NB * NS * NC];   // q bf16 (raw, then adain+scaled in-place)
__device__ __nv_bfloat16 g_kb [(size_t)2  * NS * NC];   // k bf16 (batches 0,2)
__device__ __nv_bfloat16 g_vb [(size_t)2  * NS * NC];
__device__ __nv_bfloat16 g_ob [(size_t)NB * NS * NC];   // attention out bf16
__device__ float g_mn[NB * NC];
__device__ float g_sd[NB * NC];

// ---------------- PTX helpers (baseline sm_80+, safe on sm_100) ------------
__device__ __forceinline__ uint32_t smem_u32(const void* p) {
    uint32_t a;
    asm("{ .reg .u64 t; cvta.to.shared.u64 t, %1; cvt.u32.u64 %0, t; }" : "=r"(a) : "l"(p));
    return a;
}

#define CP16(dst, src) \
    asm volatile("cp.async.cg.shared.global [%0], [%1], 16;" :: "r"(dst), "l"(src))
#define CP_COMMIT() asm volatile("cp.async.commit_group;" ::: "memory")
#define CP_WAIT1()  asm volatile("cp.async.wait_group 1;" ::: "memory")

__device__ __forceinline__ void ldm_x4(uint32_t& r0, uint32_t& r1, uint32_t& r2, uint32_t& r3, uint32_t a) {
    asm volatile("ldmatrix.sync.aligned.m8n8.x4.shared.b16 {%0,%1,%2,%3}, [%4];"
        : "=r"(r0), "=r"(r1), "=r"(r2), "=r"(r3) : "r"(a));
}
__device__ __forceinline__ void ldm_x4t(uint32_t& r0, uint32_t& r1, uint32_t& r2, uint32_t& r3, uint32_t a) {
    asm volatile("ldmatrix.sync.aligned.m8n8.x4.trans.shared.b16 {%0,%1,%2,%3}, [%4];"
        : "=r"(r0), "=r"(r1), "=r"(r2), "=r"(r3) : "r"(a));
}
__device__ __forceinline__ void mma_bf16(float* c, const uint32_t* a,
                                         uint32_t b0, uint32_t b1) {
    asm volatile("mma.sync.aligned.m16n8k16.row.col.f32.bf16.bf16.f32 "
        "{%0,%1,%2,%3}, {%4,%5,%6,%7}, {%8,%9}, {%0,%1,%2,%3};"
        : "+f"(c[0]), "+f"(c[1]), "+f"(c[2]), "+f"(c[3])
        : "r"(a[0]), "r"(a[1]), "r"(a[2]), "r"(a[3]), "r"(b0), "r"(b1));
}
__device__ __forceinline__ uint32_t packbf(float lo, float hi) {
    __nv_bfloat162 p = __floats2bfloat162_rn(lo, hi);
    return *(uint32_t*)&p;
}
__device__ __forceinline__ float ex2f(float x) {
    float r;
    asm("ex2.approx.ftz.f32 %0, %1;" : "=f"(r) : "f"(x));
    return r;
}

// ---------------- merged fp32 -> bf16 convert (hs + 4 weights) -------------
__global__ void __launch_bounds__(256) conv_all(
    const float* __restrict__ hs, const float* __restrict__ wq,
    const float* __restrict__ wk, const float* __restrict__ wv,
    const float* __restrict__ wo,
    __nv_bfloat16* __restrict__ hsb, __nv_bfloat16* __restrict__ wqb,
    __nv_bfloat16* __restrict__ wkb, __nv_bfloat16* __restrict__ wvb,
    __nv_bfloat16* __restrict__ wob)
{
    int blk = blockIdx.x;
    const float* src; __nv_bfloat16* dst; int base;
    if (blk < 5120) { src = hs; dst = hsb; base = blk; }
    else {
        int t = blk - 5120, w = t / 400;
        base = t % 400;
        src = (w == 0) ? wq : (w == 1) ? wk : (w == 2) ? wv : wo;
        dst = (w == 0) ? wqb : (w == 1) ? wkb : (w == 2) ? wvb : wob;
    }
    int i = base * 256 + threadIdx.x;
    float4 v = ((const float4*)src)[i];
    uint2 o;
    o.x = packbf(v.x, v.y);
    o.y = packbf(v.z, v.w);
    ((uint2*)dst)[i] = o;
}

// ---------------- GEMM: C[M,640] = A[M,640] @ W[640,640]^T ------------------
// MODE 2: fp32 out + bias + residual (final projection), grid (5, M/128)
// MODE 3: bf16 out, no remap (Q), grid (5, 64)
// MODE 4: bf16 out, input rows remapped to batches {0,2}; blockIdx.x<5 -> W0/out0
//         (K), else W1/out1 (V). grid (10, 32)
// 128x128 block, BK=32, 256 threads (8 warps, each 32x64), cp.async 2-stage.
template <int MODE>
__global__ void __launch_bounds__(256) gemm_mma(
    const __nv_bfloat16* __restrict__ A,
    const __nv_bfloat16* __restrict__ W0, const __nv_bfloat16* __restrict__ W1,
    const float* __restrict__ bias, const float* __restrict__ resid,
    float* __restrict__ outF,
    __nv_bfloat16* __restrict__ outB0, __nv_bfloat16* __restrict__ outB1)
{
    __shared__ __align__(16) char smem[40960];   // 2 stages x (A 10240 + B 10240)
    const uint32_t sb = smem_u32(smem);
    const int tid = threadIdx.x;
    const int w = tid >> 5, lam = tid & 31;

    const __nv_bfloat16* W = W0;
    __nv_bfloat16* outB = outB0;
    int bx = blockIdx.x;
    if (MODE == 4 && bx >= 5) { W = W1; outB = outB1; bx -= 5; }

    const int row0 = blockIdx.y * 128, col0 = bx * 128;
    const int warp_m = (w & 3) * 32, warp_n = (w >> 2) * 64;

    // loader mapping: thread -> (row tid/2, 32B half tid&1)
    const int lrow = tid >> 1;
    const int gr = row0 + lrow;
    const int arow = (MODE == 4) ? ((gr & 2047) + ((gr >> 11) << 12)) : gr;
    const char* ag = (const char*)(A + (size_t)arow * NC) + (tid & 1) * 32;
    const char* bg = (const char*)(W + (size_t)(col0 + lrow) * NC) + (tid & 1) * 32;
    const uint32_t asb = sb + lrow * 80 + (tid & 1) * 32;
    const uint32_t bsb = sb + 10240 + lrow * 80 + (tid & 1) * 32;

    float acc[2][8][4];
#pragma unroll
    for (int i = 0; i < 2; i++)
#pragma unroll
        for (int j = 0; j < 8; j++)
#pragma unroll
            for (int e = 0; e < 4; e++) acc[i][j][e] = 0.f;

#pragma unroll
    for (int s = 0; s < 2; s++) {
        uint32_t so = s * 20480;
        int kb_ = s * 64;
        CP16(asb + so, ag + kb_); CP16(asb + so + 16, ag + kb_ + 16);
        CP16(bsb + so, bg + kb_); CP16(bsb + so + 16, bg + kb_ + 16);
        CP_COMMIT();
    }

    for (int c = 0; c < 20; c++) {
        CP_WAIT1(); __syncthreads();
        const int st = c & 1;
        const uint32_t sa  = sb + st * 20480;
        const uint32_t sbm = sb + 10240 + st * 20480;
        const uint32_t aab = sa + (warp_m + (lam & 15)) * 80 + (lam >> 4) * 16;
        const uint32_t bab4 = sbm + (warp_n + (lam & 7) + ((lam >> 4) << 3)) * 80
                              + ((lam >> 3) & 1) * 16;
#pragma unroll
        for (int s = 0; s < 2; s++) {
            uint32_t a0[4], a1[4];
            ldm_x4(a0[0], a0[1], a0[2], a0[3], aab + s * 32);
            ldm_x4(a1[0], a1[1], a1[2], a1[3], aab + 16 * 80 + s * 32);
#pragma unroll
            for (int jp = 0; jp < 4; jp++) {
                uint32_t b0, b1, b2, b3;
                ldm_x4(b0, b1, b2, b3, bab4 + jp * (16 * 80) + s * 32);
                mma_bf16(acc[0][2 * jp],     a0, b0, b1);
                mma_bf16(acc[0][2 * jp + 1], a0, b2, b3);
                mma_bf16(acc[1][2 * jp],     a1, b0, b1);
                mma_bf16(acc[1][2 * jp + 1], a1, b2, b3);
            }
        }
        __syncthreads();
        if (c + 2 < 20) {
            uint32_t so = st * 20480;
            int kb_ = (c + 2) * 64;
            CP16(asb + so, ag + kb_); CP16(asb + so + 16, ag + kb_ + 16);
            CP16(bsb + so, bg + kb_); CP16(bsb + so + 16, bg + kb_ + 16);
        }
        CP_COMMIT();
    }

    const int rb = row0 + warp_m + (lam >> 2);
    const int cb = col0 + warp_n + 2 * (lam & 3);
#pragma unroll
    for (int im = 0; im < 2; im++) {
#pragma unroll
        for (int j = 0; j < 8; j++) {
            int r = rb + im * 16;
            int cc = cb + j * 8;
            float* a4 = acc[im][j];
            if (MODE == 2) {
                size_t o0 = (size_t)r * NC + cc;
                size_t o1 = (size_t)(r + 8) * NC + cc;
                float2 rv0 = *(const float2*)(resid + o0);
                float2 rv1 = *(const float2*)(resid + o1);
                float2 bv = *(const float2*)(bias + cc);
                *(float2*)(outF + o0) = make_float2(a4[0] + bv.x + rv0.x, a4[1] + bv.y + rv0.y);
                *(float2*)(outF + o1) = make_float2(a4[2] + bv.x + rv1.x, a4[3] + bv.y + rv1.y);
            } else {
                *(uint32_t*)(outB + (size_t)r * NC + cc) = packbf(a4[0], a4[1]);
                *(uint32_t*)(outB + (size_t)(r + 8) * NC + cc) = packbf(a4[2], a4[3]);
            }
        }
    }
}

// ---------------- AdaIN stats on bf16 q (over n, per (b, col)), ddof=1 ------
__global__ void __launch_bounds__(256) adain_stats2(
    const __nv_bfloat16* __restrict__ qb, float* __restrict__ mn, float* __restrict__ sd)
{
    int b  = blockIdx.x / 10;
    int cg = blockIdx.x % 10;
    int c  = cg * 64 + (threadIdx.x & 63);
    int part = threadIdx.x >> 6;
    const __nv_bfloat16* base = qb + (size_t)b * NS * NC + c;
    float s = 0.f, ss = 0.f;
    for (int n = part; n < NS; n += 4) {
        float x = __bfloat162float(base[(size_t)n * NC]);
        s += x; ss += x * x;
    }
    __shared__ float sh_s[4][64], sh_q[4][64];
    sh_s[part][threadIdx.x & 63] = s;
    sh_q[part][threadIdx.x & 63] = ss;
    __syncthreads();
    if (threadIdx.x < 64) {
        int d = threadIdx.x;
        float S  = sh_s[0][d] + sh_s[1][d] + sh_s[2][d] + sh_s[3][d];
        float Q2 = sh_q[0][d] + sh_q[1][d] + sh_q[2][d] + sh_q[3][d];
        float m   = S / (float)NS;
        float var = (Q2 - S * m) / (float)(NS - 1);
        mn[b * NC + cg * 64 + d] = m;
        sd[b * NC + cg * 64 + d] = sqrtf(var + 1e-5f);
    }
}

// ---- AdaIN apply (odd batches) + scale by log2(e)/8, in-place bf16 ---------
__global__ void __launch_bounds__(160) adain_conv(
    __nv_bfloat16* __restrict__ qb, const float* __restrict__ mn,
    const float* __restrict__ sd)
{
    int row = blockIdx.x;               // 0..8191
    int b = row >> 11;
    int c = threadIdx.x * 4;
    uint2 raw = *(const uint2*)(qb + (size_t)row * NC + c);
    __nv_bfloat162 p0 = *(__nv_bfloat162*)&raw.x;
    __nv_bfloat162 p1 = *(__nv_bfloat162*)&raw.y;
    float4 x = make_float4(__bfloat162float(p0.x), __bfloat162float(p0.y),
                           __bfloat162float(p1.x), __bfloat162float(p1.y));
    if (b & 1) {
        int src = b - 1;
        float4 mo = *(const float4*)(mn + b * NC + c);
        float4 so = *(const float4*)(sd + b * NC + c);
        float4 ms = *(const float4*)(mn + src * NC + c);
        float4 ssr = *(const float4*)(sd + src * NC + c);
        x.x = (x.x - mo.x) * (ssr.x / so.x) + ms.x;
        x.y = (x.y - mo.y) * (ssr.y / so.y) + ms.y;
        x.z = (x.z - mo.z) * (ssr.z / so.z) + ms.z;
        x.w = (x.w - mo.w) * (ssr.w / so.w) + ms.w;
    }
    uint2 o;
    o.x = packbf(x.x * QSCALE, x.y * QSCALE);
    o.y = packbf(x.z * QSCALE, x.w * QSCALE);
    *(uint2*)(qb + (size_t)row * NC + c) = o;
}

// ---------------- Flash attention via mma.sync ------------------------------
// Block: 128 q-rows of one (b,h), 256 threads (8 warps x 16 rows). BK=64.
// cp.async 2-stage KV pipeline. No-max softmax with base-2 exp (q pre-scaled
// by log2(e)/8). O accumulates in registers; one divide at the end.
__global__ void __launch_bounds__(256, 2) attn_mma(
    const __nv_bfloat16* __restrict__ q, const __nv_bfloat16* __restrict__ k,
    const __nv_bfloat16* __restrict__ v, __nv_bfloat16* __restrict__ o)
{
    extern __shared__ __align__(16) char smd[];
    // Q 128x144B @0 (18432); K0 18432, V0 27648, K1 36864, V1 46080
    const uint32_t sb = smem_u32(smd);
    const int tid = threadIdx.x, w = tid >> 5, lam = tid & 31;
    const int by = blockIdx.y;
    const int b = by / NH, h = by % NH, kb = b >> 1;
    const int q0 = blockIdx.x * 128;

    const char* qg = (const char*)(q + ((size_t)b * NS + q0 + (tid >> 1)) * NC + h * 64) + (tid & 1) * 64;
    const char* kg = (const char*)(k + ((size_t)kb * NS + (tid >> 2)) * NC + h * 64) + (tid & 3) * 32;
    const char* vg = (const char*)(v + ((size_t)kb * NS + (tid >> 2)) * NC + h * 64) + (tid & 3) * 32;
    const uint32_t qs  = sb + (tid >> 1) * 144 + (tid & 1) * 64;
    const uint32_t ksb = sb + 18432 + (tid >> 2) * 144 + (tid & 3) * 32;
    const uint32_t vsb = sb + 27648 + (tid >> 2) * 144 + (tid & 3) * 32;
    const size_t kv_step = (size_t)64 * NC * 2;

#pragma unroll
    for (int i = 0; i < 4; i++) CP16(qs + i * 16, qg + i * 16);
    CP16(ksb, kg); CP16(ksb + 16, kg + 16);
    CP16(vsb, vg); CP16(vsb + 16, vg + 16);
    CP_COMMIT();
    CP16(ksb + 18432, kg + kv_step); CP16(ksb + 18432 + 16, kg + kv_step + 16);
    CP16(vsb + 18432, vg + kv_step); CP16(vsb + 18432 + 16, vg + kv_step + 16);
    CP_COMMIT();
    CP_WAIT1(); __syncthreads();

    uint32_t aq[4][4];
    {
        uint32_t qab = sb + (w * 16 + (lam & 15)) * 144 + (lam >> 4) * 16;
#pragma unroll
        for (int t = 0; t < 4; t++)
            ldm_x4(aq[t][0], aq[t][1], aq[t][2], aq[t][3], qab + t * 32);
    }

    float oacc[8][4];
#pragma unroll
    for (int j = 0; j < 8; j++)
#pragma unroll
        for (int e = 0; e < 4; e++) oacc[j][e] = 0.f;
    float l0 = 0.f, l1 = 0.f;

    // x4 addressing: lanes 0-15 -> j-block 2jp, lanes 16-31 -> 2jp+1
    const uint32_t kab0 = sb + 18432 + ((lam & 7) + ((lam >> 4) << 3)) * 144
                          + ((lam >> 3) & 1) * 16;
    const uint32_t vab0 = sb + 27648 + (lam & 15) * 144 + (lam >> 4) * 16;

    for (int i = 0; i < 32; i++) {
        const int st = i & 1;
        const uint32_t kab = kab0 + st * 18432;
        const uint32_t vab = vab0 + st * 18432;

        // S = Q @ K^T : c[j] covers kv cols 8j..8j+7
        float c[8][4];
#pragma unroll
        for (int j = 0; j < 8; j++)
#pragma unroll
            for (int e = 0; e < 4; e++) c[j][e] = 0.f;
#pragma unroll
        for (int t = 0; t < 4; t++) {
#pragma unroll
            for (int jp = 0; jp < 4; jp++) {
                uint32_t b0, b1, b2, b3;
                ldm_x4(b0, b1, b2, b3, kab + jp * (16 * 144) + t * 32);
                mma_bf16(c[2 * jp],     aq[t], b0, b1);
                mma_bf16(c[2 * jp + 1], aq[t], b2, b3);
            }
        }
        // exp2 (no max subtraction) + row-sum partials
        float p0 = 0.f, p1 = 0.f;
#pragma unroll
        for (int j = 0; j < 8; j++) {
            c[j][0] = ex2f(c[j][0]); c[j][1] = ex2f(c[j][1]);
            c[j][2] = ex2f(c[j][2]); c[j][3] = ex2f(c[j][3]);
            p0 += c[j][0] + c[j][1];
            p1 += c[j][2] + c[j][3];
        }
        l0 += p0; l1 += p1;
        // repack C-frags (m16n8 pairs) as A-frags (m16k16) for P@V
        uint32_t ap[4][4];
#pragma unroll
        for (int t = 0; t < 4; t++) {
            ap[t][0] = packbf(c[2*t][0],   c[2*t][1]);
            ap[t][1] = packbf(c[2*t][2],   c[2*t][3]);
            ap[t][2] = packbf(c[2*t+1][0], c[2*t+1][1]);
            ap[t][3] = packbf(c[2*t+1][2], c[2*t+1][3]);
        }
        // O += P @ V  (V transposed loads: k16n8 frags, two d-blocks per x4t)
#pragma unroll
        for (int t = 0; t < 4; t++) {
#pragma unroll
            for (int jp = 0; jp < 4; jp++) {
                uint32_t b0, b1, b2, b3;
                ldm_x4t(b0, b1, b2, b3, vab + t * (16 * 144) + jp * 32);
                mma_bf16(oacc[2 * jp],     ap[t], b0, b1);
                mma_bf16(oacc[2 * jp + 1], ap[t], b2, b3);
            }
        }
        __syncthreads();
        if (i + 2 < 32) {
            const char* kgi = kg + (size_t)(i + 2) * kv_step;
            const char* vgi = vg + (size_t)(i + 2) * kv_step;
            uint32_t ko = ksb + st * 18432, vo = vsb + st * 18432;
            CP16(ko, kgi); CP16(ko + 16, kgi + 16);
            CP16(vo, vgi); CP16(vo + 16, vgi + 16);
        }
        CP_COMMIT();
        CP_WAIT1(); __syncthreads();
    }

    l0 += __shfl_xor_sync(0xffffffffu, l0, 1);
    l0 += __shfl_xor_sync(0xffffffffu, l0, 2);
    l1 += __shfl_xor_sync(0xffffffffu, l1, 1);
    l1 += __shfl_xor_sync(0xffffffffu, l1, 2);
    const float i0 = 1.f / l0, i1 = 1.f / l1;

    const int r = q0 + w * 16 + (lam >> 2);
    __nv_bfloat16* ob0 = o + ((size_t)b * NS + r) * NC + h * 64 + 2 * (lam & 3);
#pragma unroll
    for (int j = 0; j < 8; j++) {
        *(uint32_t*)(ob0 + j * 8)          = packbf(oacc[j][0] * i0, oacc[j][1] * i0);
        *(uint32_t*)(ob0 + 8 * NC + j * 8) = packbf(oacc[j][2] * i1, oacc[j][3] * i1);
    }
}

// ---------------- launch ----------------
extern "C" void kernel_launch(void* const* d_in, const int* in_sizes, int n_in,
                              void* d_out, int out_size)
{
    const float* hs = (const float*)d_in[0];
    const float* wq = (const float*)d_in[1];
    const float* wk = (const float*)d_in[2];
    const float* wv = (const float*)d_in[3];
    const float* wo = (const float*)d_in[4];
    const float* bo = (const float*)d_in[5];
    float* out = (float*)d_out;

    __nv_bfloat16 *hsb, *wqb, *wkb, *wvb, *wob, *qb, *kbp, *vbp, *obp;
    float *mn, *sd;
    cudaGetSymbolAddress((void**)&hsb, g_hsb);
    cudaGetSymbolAddress((void**)&wqb, g_wqb);
    cudaGetSymbolAddress((void**)&wkb, g_wkb);
    cudaGetSymbolAddress((void**)&wvb, g_wvb);
    cudaGetSymbolAddress((void**)&wob, g_wob);
    cudaGetSymbolAddress((void**)&qb,  g_qb);
    cudaGetSymbolAddress((void**)&kbp, g_kb);
    cudaGetSymbolAddress((void**)&vbp, g_vb);
    cudaGetSymbolAddress((void**)&obp, g_ob);
    cudaGetSymbolAddress((void**)&mn,  g_mn);
    cudaGetSymbolAddress((void**)&sd,  g_sd);

    const int ATTN_SMEM = 55296;
    cudaFuncSetAttribute(attn_mma, cudaFuncAttributeMaxDynamicSharedMemorySize, ATTN_SMEM);

    // one merged convert (hs + 4 weights)
    conv_all<<<6720, 256>>>(hs, wq, wk, wv, wo, hsb, wqb, wkb, wvb, wob);

    // Q projection -> bf16 directly
    gemm_mma<3><<<dim3(5, 64), 256>>>(hsb, wqb, nullptr, nullptr, nullptr,
                                      nullptr, qb, nullptr);
    // fused K+V projections (source batches 0,2 only)
    gemm_mma<4><<<dim3(10, 32), 256>>>(hsb, wkb, wvb, nullptr, nullptr,
                                       nullptr, kbp, vbp);

    // AdaIN on Q (stats on bf16; transform odd batches; fold qscale), in-place
    adain_stats2<<<40, 256>>>(qb, mn, sd);
    adain_conv<<<NB * NS, 160>>>(qb, mn, sd);

    // attention
    attn_mma<<<dim3(16, 40), 256, ATTN_SMEM>>>(qb, kbp, vbp, obp);

    // output projection + bias + residual (fp32)
    gemm_mma<2><<<dim3(5, 64), 256>>>(obp, wob, nullptr, bo, hs,
                                      out, nullptr, nullptr);
}

// round 5
// speedup vs baseline: 7.2047x; 1.0684x over previous
#include <cuda_runtime.h>
#include <cuda_bf16.h>
#include <math.h>
#include <stddef.h>
#include <stdint.h>

#define NB 4
#define NS 2048
#define NC 640
#define NH 10
#define ND 64

// log2(e) * attn_scale(0.125): applied to q AFTER adain; softmax uses ex2
#define QSCALE 0.1803368801111204f

// ---------------- device scratch (no allocs allowed) ----------------
__device__ __nv_bfloat16 g_hsb[(size_t)NB * NS * NC];
__device__ __nv_bfloat16 g_wqb[NC * NC];
__device__ __nv_bfloat16 g_wkb[NC * NC];
__device__ __nv_bfloat16 g_wvb[NC * NC];
__device__ __nv_bfloat16 g_wob[NC * NC];
__device__ __nv_bfloat16 g_qb [(size_t)NB * NS * NC];   // q bf16 (raw, then adain+scaled in-place)
__device__ __nv_bfloat16 g_kb [(size_t)2  * NS * NC];   // k bf16 (batches 0,2)
__device__ __nv_bfloat16 g_vb [(size_t)2  * NS * NC];
__device__ __nv_bfloat16 g_ob [(size_t)NB * NS * NC];   // attention out bf16
__device__ float g_ps[128 * NC];   // partial sums   (4 b x 32 chunks)
__device__ float g_pq[128 * NC];   // partial sq-sums
__device__ float g_mn[NB * NC];
__device__ float g_sd[NB * NC];

// ---------------- PTX helpers (baseline sm_80+, safe on sm_100) ------------
__device__ __forceinline__ uint32_t smem_u32(const void* p) {
    uint32_t a;
    asm("{ .reg .u64 t; cvta.to.shared.u64 t, %1; cvt.u32.u64 %0, t; }" : "=r"(a) : "l"(p));
    return a;
}

#define CP16(dst, src) \
    asm volatile("cp.async.cg.shared.global [%0], [%1], 16;" :: "r"(dst), "l"(src))
#define CP_COMMIT() asm volatile("cp.async.commit_group;" ::: "memory")
#define CP_WAIT1()  asm volatile("cp.async.wait_group 1;" ::: "memory")

__device__ __forceinline__ void ldm_x4(uint32_t& r0, uint32_t& r1, uint32_t& r2, uint32_t& r3, uint32_t a) {
    asm volatile("ldmatrix.sync.aligned.m8n8.x4.shared.b16 {%0,%1,%2,%3}, [%4];"
        : "=r"(r0), "=r"(r1), "=r"(r2), "=r"(r3) : "r"(a));
}
__device__ __forceinline__ void ldm_x4t(uint32_t& r0, uint32_t& r1, uint32_t& r2, uint32_t& r3, uint32_t a) {
    asm volatile("ldmatrix.sync.aligned.m8n8.x4.trans.shared.b16 {%0,%1,%2,%3}, [%4];"
        : "=r"(r0), "=r"(r1), "=r"(r2), "=r"(r3) : "r"(a));
}
__device__ __forceinline__ void mma_bf16(float* c, const uint32_t* a,
                                         uint32_t b0, uint32_t b1) {
    asm volatile("mma.sync.aligned.m16n8k16.row.col.f32.bf16.bf16.f32 "
        "{%0,%1,%2,%3}, {%4,%5,%6,%7}, {%8,%9}, {%0,%1,%2,%3};"
        : "+f"(c[0]), "+f"(c[1]), "+f"(c[2]), "+f"(c[3])
        : "r"(a[0]), "r"(a[1]), "r"(a[2]), "r"(a[3]), "r"(b0), "r"(b1));
}
__device__ __forceinline__ uint32_t packbf(float lo, float hi) {
    __nv_bfloat162 p = __floats2bfloat162_rn(lo, hi);
    return *(uint32_t*)&p;
}
__device__ __forceinline__ float ex2f(float x) {
    float r;
    asm("ex2.approx.ftz.f32 %0, %1;" : "=f"(r) : "f"(x));
    return r;
}

// ---------------- merged fp32 -> bf16 convert (hs + 4 weights) -------------
__global__ void __launch_bounds__(256) conv_all(
    const float* __restrict__ hs, const float* __restrict__ wq,
    const float* __restrict__ wk, const float* __restrict__ wv,
    const float* __restrict__ wo,
    __nv_bfloat16* __restrict__ hsb, __nv_bfloat16* __restrict__ wqb,
    __nv_bfloat16* __restrict__ wkb, __nv_bfloat16* __restrict__ wvb,
    __nv_bfloat16* __restrict__ wob)
{
    int blk = blockIdx.x;
    const float* src; __nv_bfloat16* dst; int base;
    if (blk < 5120) { src = hs; dst = hsb; base = blk; }
    else {
        int t = blk - 5120, w = t / 400;
        base = t % 400;
        src = (w == 0) ? wq : (w == 1) ? wk : (w == 2) ? wv : wo;
        dst = (w == 0) ? wqb : (w == 1) ? wkb : (w == 2) ? wvb : wob;
    }
    int i = base * 256 + threadIdx.x;
    float4 v = ((const float4*)src)[i];
    uint2 o;
    o.x = packbf(v.x, v.y);
    o.y = packbf(v.z, v.w);
    ((uint2*)dst)[i] = o;
}

// ---------------- GEMM: C[M,640] = A[M,640] @ W[640,640]^T ------------------
// MODE 2: fp32 out + bias + residual (final projection), grid (5, 64)
// MODE 3: bf16 out, no remap (Q), grid (5, 64)
// MODE 4: bf16 out, input rows remapped to batches {0,2}; blockIdx.x<5 -> W0/out0
//         (K), else W1/out1 (V). grid (10, 32)
// 128x128 block, BK=32, 256 threads (8 warps, each 32x64), cp.async 2-stage.
template <int MODE>
__global__ void __launch_bounds__(256) gemm_mma(
    const __nv_bfloat16* __restrict__ A,
    const __nv_bfloat16* __restrict__ W0, const __nv_bfloat16* __restrict__ W1,
    const float* __restrict__ bias, const float* __restrict__ resid,
    float* __restrict__ outF,
    __nv_bfloat16* __restrict__ outB0, __nv_bfloat16* __restrict__ outB1)
{
    __shared__ __align__(16) char smem[40960];   // 2 stages x (A 10240 + B 10240)
    const uint32_t sb = smem_u32(smem);
    const int tid = threadIdx.x;
    const int w = tid >> 5, lam = tid & 31;

    const __nv_bfloat16* W = W0;
    __nv_bfloat16* outB = outB0;
    int bx = blockIdx.x;
    if (MODE == 4 && bx >= 5) { W = W1; outB = outB1; bx -= 5; }

    const int row0 = blockIdx.y * 128, col0 = bx * 128;
    const int warp_m = (w & 3) * 32, warp_n = (w >> 2) * 64;

    const int lrow = tid >> 1;
    const int gr = row0 + lrow;
    const int arow = (MODE == 4) ? ((gr & 2047) + ((gr >> 11) << 12)) : gr;
    const char* ag = (const char*)(A + (size_t)arow * NC) + (tid & 1) * 32;
    const char* bg = (const char*)(W + (size_t)(col0 + lrow) * NC) + (tid & 1) * 32;
    const uint32_t asb = sb + lrow * 80 + (tid & 1) * 32;
    const uint32_t bsb = sb + 10240 + lrow * 80 + (tid & 1) * 32;

    float acc[2][8][4];
#pragma unroll
    for (int i = 0; i < 2; i++)
#pragma unroll
        for (int j = 0; j < 8; j++)
#pragma unroll
            for (int e = 0; e < 4; e++) acc[i][j][e] = 0.f;

#pragma unroll
    for (int s = 0; s < 2; s++) {
        uint32_t so = s * 20480;
        int kb_ = s * 64;
        CP16(asb + so, ag + kb_); CP16(asb + so + 16, ag + kb_ + 16);
        CP16(bsb + so, bg + kb_); CP16(bsb + so + 16, bg + kb_ + 16);
        CP_COMMIT();
    }

    for (int c = 0; c < 20; c++) {
        CP_WAIT1(); __syncthreads();
        const int st = c & 1;
        const uint32_t sa  = sb + st * 20480;
        const uint32_t sbm = sb + 10240 + st * 20480;
        const uint32_t aab = sa + (warp_m + (lam & 15)) * 80 + (lam >> 4) * 16;
        const uint32_t bab4 = sbm + (warp_n + (lam & 7) + ((lam >> 4) << 3)) * 80
                              + ((lam >> 3) & 1) * 16;
#pragma unroll
        for (int s = 0; s < 2; s++) {
            uint32_t a0[4], a1[4];
            ldm_x4(a0[0], a0[1], a0[2], a0[3], aab + s * 32);
            ldm_x4(a1[0], a1[1], a1[2], a1[3], aab + 16 * 80 + s * 32);
#pragma unroll
            for (int jp = 0; jp < 4; jp++) {
                uint32_t b0, b1, b2, b3;
                ldm_x4(b0, b1, b2, b3, bab4 + jp * (16 * 80) + s * 32);
                mma_bf16(acc[0][2 * jp],     a0, b0, b1);
                mma_bf16(acc[0][2 * jp + 1], a0, b2, b3);
                mma_bf16(acc[1][2 * jp],     a1, b0, b1);
                mma_bf16(acc[1][2 * jp + 1], a1, b2, b3);
            }
        }
        __syncthreads();
        if (c + 2 < 20) {
            uint32_t so = st * 20480;
            int kb_ = (c + 2) * 64;
            CP16(asb + so, ag + kb_); CP16(asb + so + 16, ag + kb_ + 16);
            CP16(bsb + so, bg + kb_); CP16(bsb + so + 16, bg + kb_ + 16);
        }
        CP_COMMIT();
    }

    const int rb = row0 + warp_m + (lam >> 2);
    const int cb = col0 + warp_n + 2 * (lam & 3);
#pragma unroll
    for (int im = 0; im < 2; im++) {
#pragma unroll
        for (int j = 0; j < 8; j++) {
            int r = rb + im * 16;
            int cc = cb + j * 8;
            float* a4 = acc[im][j];
            if (MODE == 2) {
                size_t o0 = (size_t)r * NC + cc;
                size_t o1 = (size_t)(r + 8) * NC + cc;
                float2 rv0 = *(const float2*)(resid + o0);
                float2 rv1 = *(const float2*)(resid + o1);
                float2 bv = *(const float2*)(bias + cc);
                *(float2*)(outF + o0) = make_float2(a4[0] + bv.x + rv0.x, a4[1] + bv.y + rv0.y);
                *(float2*)(outF + o1) = make_float2(a4[2] + bv.x + rv1.x, a4[3] + bv.y + rv1.y);
            } else {
                *(uint32_t*)(outB + (size_t)r * NC + cc) = packbf(a4[0], a4[1]);
                *(uint32_t*)(outB + (size_t)(r + 8) * NC + cc) = packbf(a4[2], a4[3]);
            }
        }
    }
}

// ------------- AdaIN stats pass 1: coalesced partial sums -------------------
// 128 blocks = 4 batches x 32 chunks of 64 rows. 320 threads: thread t owns
// columns 2t, 2t+1 (one uint32 = 2 bf16 per row). Fully coalesced rows.
__global__ void __launch_bounds__(320) adain_p1(
    const __nv_bfloat16* __restrict__ qb, float* __restrict__ ps, float* __restrict__ pq)
{
    const int blk = blockIdx.x;            // b = blk>>5, chunk = blk&31
    const int b = blk >> 5, ch = blk & 31;
    const uint32_t* p = (const uint32_t*)(qb + (((size_t)b * NS) + ch * 64) * NC) + threadIdx.x;
    float s0 = 0.f, s1 = 0.f, q0 = 0.f, q1 = 0.f;
#pragma unroll 8
    for (int r = 0; r < 64; r++) {
        uint32_t u = p[r * 320];
        __nv_bfloat162 h = *(__nv_bfloat162*)&u;
        float x0 = __bfloat162float(h.x), x1 = __bfloat162float(h.y);
        s0 += x0; q0 += x0 * x0;
        s1 += x1; q1 += x1 * x1;
    }
    *(float2*)(ps + blk * NC + 2 * threadIdx.x) = make_float2(s0, s1);
    *(float2*)(pq + blk * NC + 2 * threadIdx.x) = make_float2(q0, q1);
}

// ------------- AdaIN stats pass 2: finalize over 32 chunks ------------------
__global__ void __launch_bounds__(256) adain_p2(
    const float* __restrict__ ps, const float* __restrict__ pq,
    float* __restrict__ mn, float* __restrict__ sd)
{
    int i = blockIdx.x * 256 + threadIdx.x;    // 0..2559 = b*640 + c
    if (i >= NB * NC) return;
    int b = i / NC, c = i % NC;
    float S = 0.f, Q = 0.f;
#pragma unroll 8
    for (int j = 0; j < 32; j++) {
        S += ps[(b * 32 + j) * NC + c];
        Q += pq[(b * 32 + j) * NC + c];
    }
    float m   = S / (float)NS;
    float var = (Q - S * m) / (float)(NS - 1);
    mn[i] = m;
    sd[i] = sqrtf(var + 1e-5f);
}

// ---- AdaIN apply (odd batches) + scale by log2(e)/8, in-place bf16 ---------
__global__ void __launch_bounds__(160) adain_conv(
    __nv_bfloat16* __restrict__ qb, const float* __restrict__ mn,
    const float* __restrict__ sd)
{
    int row = blockIdx.x;               // 0..8191
    int b = row >> 11;
    int c = threadIdx.x * 4;
    uint2 raw = *(const uint2*)(qb + (size_t)row * NC + c);
    __nv_bfloat162 p0 = *(__nv_bfloat162*)&raw.x;
    __nv_bfloat162 p1 = *(__nv_bfloat162*)&raw.y;
    float4 x = make_float4(__bfloat162float(p0.x), __bfloat162float(p0.y),
                           __bfloat162float(p1.x), __bfloat162float(p1.y));
    if (b & 1) {
        int src = b - 1;
        float4 mo = *(const float4*)(mn + b * NC + c);
        float4 so = *(const float4*)(sd + b * NC + c);
        float4 ms = *(const float4*)(mn + src * NC + c);
        float4 ssr = *(const float4*)(sd + src * NC + c);
        x.x = (x.x - mo.x) * (ssr.x / so.x) + ms.x;
        x.y = (x.y - mo.y) * (ssr.y / so.y) + ms.y;
        x.z = (x.z - mo.z) * (ssr.z / so.z) + ms.z;
        x.w = (x.w - mo.w) * (ssr.w / so.w) + ms.w;
    }
    uint2 o;
    o.x = packbf(x.x * QSCALE, x.y * QSCALE);
    o.y = packbf(x.z * QSCALE, x.w * QSCALE);
    *(uint2*)(qb + (size_t)row * NC + c) = o;
}

// ---------------- Flash attention via mma.sync ------------------------------
// Block: 128 q-rows of one (b,h), 256 threads (8 warps x 16 rows). BK=64.
// 3-stage cp.async KV pipeline with early prefetch (load i+2 issued BEFORE
// compute i). No-max softmax with base-2 exp. O in registers; divide at end.
__global__ void __launch_bounds__(256, 2) attn_mma(
    const __nv_bfloat16* __restrict__ q, const __nv_bfloat16* __restrict__ k,
    const __nv_bfloat16* __restrict__ v, __nv_bfloat16* __restrict__ o)
{
    extern __shared__ __align__(16) char smd[];
    // Q 128x144B @0 (18432); stage s (0..2): K @18432+s*18432, V @+9216
    const uint32_t sb = smem_u32(smd);
    const int tid = threadIdx.x, w = tid >> 5, lam = tid & 31;
    const int by = blockIdx.y;
    const int b = by / NH, h = by % NH, kb = b >> 1;
    const int q0 = blockIdx.x * 128;

    const char* qg = (const char*)(q + ((size_t)b * NS + q0 + (tid >> 1)) * NC + h * 64) + (tid & 1) * 64;
    const char* kg = (const char*)(k + ((size_t)kb * NS + (tid >> 2)) * NC + h * 64) + (tid & 3) * 32;
    const char* vg = (const char*)(v + ((size_t)kb * NS + (tid >> 2)) * NC + h * 64) + (tid & 3) * 32;
    const uint32_t qs  = sb + (tid >> 1) * 144 + (tid & 1) * 64;
    const uint32_t ksb = sb + 18432 + (tid >> 2) * 144 + (tid & 3) * 32;
    const uint32_t vsb = ksb + 9216;
    const size_t kv_step = (size_t)64 * NC * 2;

    // prologue: Q + tile0 (stage0), tile1 (stage1)
#pragma unroll
    for (int i = 0; i < 4; i++) CP16(qs + i * 16, qg + i * 16);
    CP16(ksb, kg); CP16(ksb + 16, kg + 16);
    CP16(vsb, vg); CP16(vsb + 16, vg + 16);
    CP_COMMIT();
    CP16(ksb + 18432, kg + kv_step); CP16(ksb + 18432 + 16, kg + kv_step + 16);
    CP16(vsb + 18432, vg + kv_step); CP16(vsb + 18432 + 16, vg + kv_step + 16);
    CP_COMMIT();
    CP_WAIT1(); __syncthreads();

    uint32_t aq[4][4];
    {
        uint32_t qab = sb + (w * 16 + (lam & 15)) * 144 + (lam >> 4) * 16;
#pragma unroll
        for (int t = 0; t < 4; t++)
            ldm_x4(aq[t][0], aq[t][1], aq[t][2], aq[t][3], qab + t * 32);
    }

    float oacc[8][4];
#pragma unroll
    for (int j = 0; j < 8; j++)
#pragma unroll
        for (int e = 0; e < 4; e++) oacc[j][4 - 4] = oacc[j][0], oacc[j][0] = 0.f, oacc[j][1] = 0.f, oacc[j][2] = 0.f, oacc[j][3] = 0.f;
    float l0 = 0.f, l1 = 0.f;

    const uint32_t kab0 = sb + 18432 + ((lam & 7) + ((lam >> 4) << 3)) * 144
                          + ((lam >> 3) & 1) * 16;
    const uint32_t vab0 = sb + 18432 + 9216 + (lam & 15) * 144 + (lam >> 4) * 16;

    int st = 0;          // stage of current tile i
    for (int i = 0; i < 32; i++) {
        // early prefetch: tile i+2 into stage (i+2)%3 (free: consumed at i-1)
        const int pf = (st + 2 >= 3) ? st - 1 : st + 2;
        if (i + 2 < 32) {
            const char* kgi = kg + (size_t)(i + 2) * kv_step;
            const char* vgi = vg + (size_t)(i + 2) * kv_step;
            uint32_t ko = ksb + pf * 18432, vo = vsb + pf * 18432;
            CP16(ko, kgi); CP16(ko + 16, kgi + 16);
            CP16(vo, vgi); CP16(vo + 16, vgi + 16);
        }
        CP_COMMIT();

        const uint32_t kab = kab0 + st * 18432;
        const uint32_t vab = vab0 + st * 18432;

        // S = Q @ K^T : c[j] covers kv cols 8j..8j+7
        float c[8][4];
#pragma unroll
        for (int j = 0; j < 8; j++)
#pragma unroll
            for (int e = 0; e < 4; e++) c[j][e] = 0.f;
#pragma unroll
        for (int t = 0; t < 4; t++) {
#pragma unroll
            for (int jp = 0; jp < 4; jp++) {
                uint32_t b0, b1, b2, b3;
                ldm_x4(b0, b1, b2, b3, kab + jp * (16 * 144) + t * 32);
                mma_bf16(c[2 * jp],     aq[t], b0, b1);
                mma_bf16(c[2 * jp + 1], aq[t], b2, b3);
            }
        }
        float p0 = 0.f, p1 = 0.f;
#pragma unroll
        for (int j = 0; j < 8; j++) {
            c[j][0] = ex2f(c[j][0]); c[j][1] = ex2f(c[j][1]);
            c[j][2] = ex2f(c[j][2]); c[j][3] = ex2f(c[j][3]);
            p0 += c[j][0] + c[j][1];
            p1 += c[j][2] + c[j][3];
        }
        l0 += p0; l1 += p1;
        uint32_t ap[4][4];
#pragma unroll
        for (int t = 0; t < 4; t++) {
            ap[t][0] = packbf(c[2*t][0],   c[2*t][1]);
            ap[t][1] = packbf(c[2*t][2],   c[2*t][3]);
            ap[t][2] = packbf(c[2*t+1][0], c[2*t+1][1]);
            ap[t][3] = packbf(c[2*t+1][2], c[2*t+1][3]);
        }
#pragma unroll
        for (int t = 0; t < 4; t++) {
#pragma unroll
            for (int jp = 0; jp < 4; jp++) {
                uint32_t b0, b1, b2, b3;
                ldm_x4t(b0, b1, b2, b3, vab + t * (16 * 144) + jp * 32);
                mma_bf16(oacc[2 * jp],     ap[t], b0, b1);
                mma_bf16(oacc[2 * jp + 1], ap[t], b2, b3);
            }
        }
        CP_WAIT1(); __syncthreads();
        st = (st + 1 >= 3) ? 0 : st + 1;
    }

    l0 += __shfl_xor_sync(0xffffffffu, l0, 1);
    l0 += __shfl_xor_sync(0xffffffffu, l0, 2);
    l1 += __shfl_xor_sync(0xffffffffu, l1, 1);
    l1 += __shfl_xor_sync(0xffffffffu, l1, 2);
    const float i0 = 1.f / l0, i1 = 1.f / l1;

    const int r = q0 + w * 16 + (lam >> 2);
    __nv_bfloat16* ob0 = o + ((size_t)b * NS + r) * NC + h * 64 + 2 * (lam & 3);
#pragma unroll
    for (int j = 0; j < 8; j++) {
        *(uint32_t*)(ob0 + j * 8)          = packbf(oacc[j][0] * i0, oacc[j][1] * i0);
        *(uint32_t*)(ob0 + 8 * NC + j * 8) = packbf(oacc[j][2] * i1, oacc[j][3] * i1);
    }
}

// ---------------- launch ----------------
extern "C" void kernel_launch(void* const* d_in, const int* in_sizes, int n_in,
                              void* d_out, int out_size)
{
    const float* hs = (const float*)d_in[0];
    const float* wq = (const float*)d_in[1];
    const float* wk = (const float*)d_in[2];
    const float* wv = (const float*)d_in[3];
    const float* wo = (const float*)d_in[4];
    const float* bo = (const float*)d_in[5];
    float* out = (float*)d_out;

    __nv_bfloat16 *hsb, *wqb, *wkb, *wvb, *wob, *qb, *kbp, *vbp, *obp;
    float *mn, *sd, *ps, *pq;
    cudaGetSymbolAddress((void**)&hsb, g_hsb);
    cudaGetSymbolAddress((void**)&wqb, g_wqb);
    cudaGetSymbolAddress((void**)&wkb, g_wkb);
    cudaGetSymbolAddress((void**)&wvb, g_wvb);
    cudaGetSymbolAddress((void**)&wob, g_wob);
    cudaGetSymbolAddress((void**)&qb,  g_qb);
    cudaGetSymbolAddress((void**)&kbp, g_kb);
    cudaGetSymbolAddress((void**)&vbp, g_vb);
    cudaGetSymbolAddress((void**)&obp, g_ob);
    cudaGetSymbolAddress((void**)&mn,  g_mn);
    cudaGetSymbolAddress((void**)&sd,  g_sd);
    cudaGetSymbolAddress((void**)&ps,  g_ps);
    cudaGetSymbolAddress((void**)&pq,  g_pq);

    const int ATTN_SMEM = 18432 + 3 * 18432;   // 73728
    cudaFuncSetAttribute(attn_mma, cudaFuncAttributeMaxDynamicSharedMemorySize, ATTN_SMEM);

    // one merged convert (hs + 4 weights)
    conv_all<<<6720, 256>>>(hs, wq, wk, wv, wo, hsb, wqb, wkb, wvb, wob);

    // Q projection -> bf16 directly
    gemm_mma<3><<<dim3(5, 64), 256>>>(hsb, wqb, nullptr, nullptr, nullptr,
                                      nullptr, qb, nullptr);
    // fused K+V projections (source batches 0,2 only)
    gemm_mma<4><<<dim3(10, 32), 256>>>(hsb, wkb, wvb, nullptr, nullptr,
                                       nullptr, kbp, vbp);

    // AdaIN stats (coalesced 2-pass) + apply (odd batches, fold qscale)
    adain_p1<<<128, 320>>>(qb, ps, pq);
    adain_p2<<<10, 256>>>(ps, pq, mn, sd);
    adain_conv<<<NB * NS, 160>>>(qb, mn, sd);

    // attention
    attn_mma<<<dim3(16, 40), 256, ATTN_SMEM>>>(qb, kbp, vbp, obp);

    // output projection + bias + residual (fp32)
    gemm_mma<2><<<dim3(5, 64), 256>>>(obp, wob, nullptr, bo, hs,
                                      out, nullptr, nullptr);
}

// round 6
// speedup vs baseline: 7.4557x; 1.0348x over previous
#include <cuda_runtime.h>
#include <cuda_bf16.h>
#include <math.h>
#include <stddef.h>
#include <stdint.h>

#define NB 4
#define NS 2048
#define NC 640
#define NH 10
#define ND 64

// log2(e) * attn_scale(0.125): folded into adain coeffs; softmax uses ex2
#define QSCALE 0.1803368801111204f

// ---------------- device scratch (no allocs allowed) ----------------
__device__ __nv_bfloat16 g_hsb[(size_t)NB * NS * NC];
__device__ __nv_bfloat16 g_wqb[NC * NC];
__device__ __nv_bfloat16 g_wkb[NC * NC];
__device__ __nv_bfloat16 g_wvb[NC * NC];
__device__ __nv_bfloat16 g_wob[NC * NC];
__device__ __nv_bfloat16 g_qb [(size_t)NB * NS * NC];   // q bf16 (raw projection)
__device__ __nv_bfloat16 g_kb [(size_t)2  * NS * NC];   // k bf16 (batches 0,2)
__device__ __nv_bfloat16 g_vb [(size_t)2  * NS * NC];
__device__ __nv_bfloat16 g_ob [(size_t)NB * NS * NC];   // attention out bf16
__device__ float g_ps[512 * NC];   // partial sums   (4 b x 128 chunks)
__device__ float g_pq[512 * NC];   // partial sq-sums
__device__ float g_A[NB * NC];     // per-(b,channel) affine scale (incl QSCALE)
__device__ float g_B[NB * NC];     // per-(b,channel) affine bias  (incl QSCALE)

// ---------------- PTX helpers (baseline sm_80+, safe on sm_100) ------------
__device__ __forceinline__ uint32_t smem_u32(const void* p) {
    uint32_t a;
    asm("{ .reg .u64 t; cvta.to.shared.u64 t, %1; cvt.u32.u64 %0, t; }" : "=r"(a) : "l"(p));
    return a;
}

#define CP16(dst, src) \
    asm volatile("cp.async.cg.shared.global [%0], [%1], 16;" :: "r"(dst), "l"(src))
#define CP_COMMIT() asm volatile("cp.async.commit_group;" ::: "memory")
#define CP_WAIT1()  asm volatile("cp.async.wait_group 1;" ::: "memory")

__device__ __forceinline__ void ldm_x4(uint32_t& r0, uint32_t& r1, uint32_t& r2, uint32_t& r3, uint32_t a) {
    asm volatile("ldmatrix.sync.aligned.m8n8.x4.shared.b16 {%0,%1,%2,%3}, [%4];"
        : "=r"(r0), "=r"(r1), "=r"(r2), "=r"(r3) : "r"(a));
}
__device__ __forceinline__ void ldm_x4t(uint32_t& r0, uint32_t& r1, uint32_t& r2, uint32_t& r3, uint32_t a) {
    asm volatile("ldmatrix.sync.aligned.m8n8.x4.trans.shared.b16 {%0,%1,%2,%3}, [%4];"
        : "=r"(r0), "=r"(r1), "=r"(r2), "=r"(r3) : "r"(a));
}
__device__ __forceinline__ void mma_bf16(float* c, const uint32_t* a,
                                         uint32_t b0, uint32_t b1) {
    asm volatile("mma.sync.aligned.m16n8k16.row.col.f32.bf16.bf16.f32 "
        "{%0,%1,%2,%3}, {%4,%5,%6,%7}, {%8,%9}, {%0,%1,%2,%3};"
        : "+f"(c[0]), "+f"(c[1]), "+f"(c[2]), "+f"(c[3])
        : "r"(a[0]), "r"(a[1]), "r"(a[2]), "r"(a[3]), "r"(b0), "r"(b1));
}
__device__ __forceinline__ uint32_t packbf(float lo, float hi) {
    __nv_bfloat162 p = __floats2bfloat162_rn(lo, hi);
    return *(uint32_t*)&p;
}
__device__ __forceinline__ float ex2f(float x) {
    float r;
    asm("ex2.approx.ftz.f32 %0, %1;" : "=f"(r) : "f"(x));
    return r;
}
__device__ __forceinline__ float bf2f(uint16_t u) {
    __nv_bfloat16 h = *(__nv_bfloat16*)&u;
    return __bfloat162float(h);
}

// ---------------- merged fp32 -> bf16 convert (hs + 4 weights) -------------
__global__ void __launch_bounds__(256) conv_all(
    const float* __restrict__ hs, const float* __restrict__ wq,
    const float* __restrict__ wk, const float* __restrict__ wv,
    const float* __restrict__ wo,
    __nv_bfloat16* __restrict__ hsb, __nv_bfloat16* __restrict__ wqb,
    __nv_bfloat16* __restrict__ wkb, __nv_bfloat16* __restrict__ wvb,
    __nv_bfloat16* __restrict__ wob)
{
    int blk = blockIdx.x;
    const float* src; __nv_bfloat16* dst; int base;
    if (blk < 5120) { src = hs; dst = hsb; base = blk; }
    else {
        int t = blk - 5120, w = t / 400;
        base = t % 400;
        src = (w == 0) ? wq : (w == 1) ? wk : (w == 2) ? wv : wo;
        dst = (w == 0) ? wqb : (w == 1) ? wkb : (w == 2) ? wvb : wob;
    }
    int i = base * 256 + threadIdx.x;
    float4 v = ((const float4*)src)[i];
    uint2 o;
    o.x = packbf(v.x, v.y);
    o.y = packbf(v.z, v.w);
    ((uint2*)dst)[i] = o;
}

// ---------------- GEMM: C[M,640] = A[M,640] @ W[640,640]^T ------------------
// MODE 2: fp32 out + bias + residual (final projection), grid (5, 64); W=Wk slot.
// MODE 5: merged QKV. grid (10, 64):
//   by <  32 : K/V path (rows remapped to source batches {0,2}):
//              bx<5 -> Wk/outK else Wv/outV; col0=(bx%5)*128; row0=by*128
//   by >= 32 : Q path: Wq/outQ; col0=(bx%5)*128; row0=((by-32)*2+(bx/5))*128
// 128x128 block, BK=32, 256 threads (8 warps, each 32x64), cp.async 2-stage.
template <int MODE>
__global__ void __launch_bounds__(256) gemm_mma(
    const __nv_bfloat16* __restrict__ Ain,
    const __nv_bfloat16* __restrict__ Wk, const __nv_bfloat16* __restrict__ Wv,
    const __nv_bfloat16* __restrict__ Wq,
    const float* __restrict__ bias, const float* __restrict__ resid,
    float* __restrict__ outF,
    __nv_bfloat16* __restrict__ outK, __nv_bfloat16* __restrict__ outV,
    __nv_bfloat16* __restrict__ outQ)
{
    __shared__ __align__(16) char smem[40960];   // 2 stages x (A 10240 + B 10240)
    const uint32_t sb = smem_u32(smem);
    const int tid = threadIdx.x;
    const int w = tid >> 5, lam = tid & 31;

    const __nv_bfloat16* W;
    __nv_bfloat16* outB = nullptr;
    int row0, col0;
    bool remap = false;
    if (MODE == 5) {
        int bx = blockIdx.x, by = blockIdx.y;
        col0 = (bx % 5) * 128;
        if (by < 32) {
            W = (bx < 5) ? Wk : Wv;
            outB = (bx < 5) ? outK : outV;
            row0 = by * 128;
            remap = true;
        } else {
            W = Wq; outB = outQ;
            row0 = ((by - 32) * 2 + (bx / 5)) * 128;
        }
    } else {
        W = Wk;
        row0 = blockIdx.y * 128; col0 = blockIdx.x * 128;
    }

    const int warp_m = (w & 3) * 32, warp_n = (w >> 2) * 64;

    const int lrow = tid >> 1;
    const int gr = row0 + lrow;
    const int arow = remap ? ((gr & 2047) + ((gr >> 11) << 12)) : gr;
    const char* ag = (const char*)(Ain + (size_t)arow * NC) + (tid & 1) * 32;
    const char* bg = (const char*)(W + (size_t)(col0 + lrow) * NC) + (tid & 1) * 32;
    const uint32_t asb = sb + lrow * 80 + (tid & 1) * 32;
    const uint32_t bsb = sb + 10240 + lrow * 80 + (tid & 1) * 32;

    float acc[2][8][4];
#pragma unroll
    for (int i = 0; i < 2; i++)
#pragma unroll
        for (int j = 0; j < 8; j++)
#pragma unroll
            for (int e = 0; e < 4; e++) acc[i][j][e] = 0.f;

#pragma unroll
    for (int s = 0; s < 2; s++) {
        uint32_t so = s * 20480;
        int kb_ = s * 64;
        CP16(asb + so, ag + kb_); CP16(asb + so + 16, ag + kb_ + 16);
        CP16(bsb + so, bg + kb_); CP16(bsb + so + 16, bg + kb_ + 16);
        CP_COMMIT();
    }

    for (int c = 0; c < 20; c++) {
        CP_WAIT1(); __syncthreads();
        const int st = c & 1;
        const uint32_t sa  = sb + st * 20480;
        const uint32_t sbm = sb + 10240 + st * 20480;
        const uint32_t aab = sa + (warp_m + (lam & 15)) * 80 + (lam >> 4) * 16;
        const uint32_t bab4 = sbm + (warp_n + (lam & 7) + ((lam >> 4) << 3)) * 80
                              + ((lam >> 3) & 1) * 16;
#pragma unroll
        for (int s = 0; s < 2; s++) {
            uint32_t a0[4], a1[4];
            ldm_x4(a0[0], a0[1], a0[2], a0[3], aab + s * 32);
            ldm_x4(a1[0], a1[1], a1[2], a1[3], aab + 16 * 80 + s * 32);
#pragma unroll
            for (int jp = 0; jp < 4; jp++) {
                uint32_t b0, b1, b2, b3;
                ldm_x4(b0, b1, b2, b3, bab4 + jp * (16 * 80) + s * 32);
                mma_bf16(acc[0][2 * jp],     a0, b0, b1);
                mma_bf16(acc[0][2 * jp + 1], a0, b2, b3);
                mma_bf16(acc[1][2 * jp],     a1, b0, b1);
                mma_bf16(acc[1][2 * jp + 1], a1, b2, b3);
            }
        }
        __syncthreads();
        if (c + 2 < 20) {
            uint32_t so = st * 20480;
            int kb_ = (c + 2) * 64;
            CP16(asb + so, ag + kb_); CP16(asb + so + 16, ag + kb_ + 16);
            CP16(bsb + so, bg + kb_); CP16(bsb + so + 16, bg + kb_ + 16);
        }
        CP_COMMIT();
    }

    const int rb = row0 + warp_m + (lam >> 2);
    const int cb = col0 + warp_n + 2 * (lam & 3);
#pragma unroll
    for (int im = 0; im < 2; im++) {
#pragma unroll
        for (int j = 0; j < 8; j++) {
            int r = rb + im * 16;
            int cc = cb + j * 8;
            float* a4 = acc[im][j];
            if (MODE == 2) {
                size_t o0 = (size_t)r * NC + cc;
                size_t o1 = (size_t)(r + 8) * NC + cc;
                float2 rv0 = *(const float2*)(resid + o0);
                float2 rv1 = *(const float2*)(resid + o1);
                float2 bv = *(const float2*)(bias + cc);
                *(float2*)(outF + o0) = make_float2(a4[0] + bv.x + rv0.x, a4[1] + bv.y + rv0.y);
                *(float2*)(outF + o1) = make_float2(a4[2] + bv.x + rv1.x, a4[3] + bv.y + rv1.y);
            } else {
                *(uint32_t*)(outB + (size_t)r * NC + cc) = packbf(a4[0], a4[1]);
                *(uint32_t*)(outB + (size_t)(r + 8) * NC + cc) = packbf(a4[2], a4[3]);
            }
        }
    }
}

// ------------- AdaIN stats pass 1: coalesced partial sums -------------------
// 512 blocks = 4 batches x 128 chunks of 16 rows. 320 threads: thread t owns
// columns 2t, 2t+1 (one uint32 = 2 bf16 per row). Fully coalesced rows.
__global__ void __launch_bounds__(320) adain_p1(
    const __nv_bfloat16* __restrict__ qb, float* __restrict__ ps, float* __restrict__ pq)
{
    const int blk = blockIdx.x;            // b = blk>>7, chunk = blk&127
    const int b = blk >> 7, ch = blk & 127;
    const uint32_t* p = (const uint32_t*)(qb + (((size_t)b * NS) + ch * 16) * NC) + threadIdx.x;
    float s0 = 0.f, s1 = 0.f, q0 = 0.f, q1 = 0.f;
#pragma unroll
    for (int r = 0; r < 16; r++) {
        uint32_t u = p[r * 320];
        __nv_bfloat162 h = *(__nv_bfloat162*)&u;
        float x0 = __bfloat162float(h.x), x1 = __bfloat162float(h.y);
        s0 += x0; q0 += x0 * x0;
        s1 += x1; q1 += x1 * x1;
    }
    *(float2*)(ps + blk * NC + 2 * threadIdx.x) = make_float2(s0, s1);
    *(float2*)(pq + blk * NC + 2 * threadIdx.x) = make_float2(q0, q1);
}

// ------------- AdaIN stats pass 2: finalize -> affine coeffs ----------------
// Per (b,c): A = QSCALE * sd_src/sd_own, B = QSCALE*(m_src - m_own*sd_src/sd_own)
// Even batches: identity (A = QSCALE, B = 0).
__global__ void __launch_bounds__(256) adain_p2(
    const float* __restrict__ ps, const float* __restrict__ pq,
    float* __restrict__ Ac, float* __restrict__ Bc)
{
    int i = blockIdx.x * 256 + threadIdx.x;    // 0..2559 = b*640 + c
    if (i >= NB * NC) return;
    int b = i / NC, c = i % NC;
    float S = 0.f, Q = 0.f;
#pragma unroll 8
    for (int j = 0; j < 128; j++) {
        S += ps[(b * 128 + j) * NC + c];
        Q += pq[(b * 128 + j) * NC + c];
    }
    float m   = S / (float)NS;
    float var = (Q - S * m) / (float)(NS - 1);
    float sdv = sqrtf(var + 1e-5f);
    float Acoef = QSCALE, Bcoef = 0.f;
    if (b & 1) {
        int bs = b - 1;
        float Ss = 0.f, Qs = 0.f;
#pragma unroll 8
        for (int j = 0; j < 128; j++) {
            Ss += ps[(bs * 128 + j) * NC + c];
            Qs += pq[(bs * 128 + j) * NC + c];
        }
        float ms   = Ss / (float)NS;
        float vars = (Qs - Ss * ms) / (float)(NS - 1);
        float sds  = sqrtf(vars + 1e-5f);
        float r = sds / sdv;
        Acoef = QSCALE * r;
        Bcoef = QSCALE * (ms - m * r);
    }
    Ac[i] = Acoef;
    Bc[i] = Bcoef;
}

// ---------------- Flash attention via mma.sync ------------------------------
// Block: 128 q-rows of one (b,h), 256 threads (8 warps x 16 rows). BK=64.
// AdaIN-apply fused into Q smem staging (affine coeffs from adain_p2).
// 3-stage cp.async KV pipeline with early prefetch. No-max base-2 softmax.
__global__ void __launch_bounds__(256, 2) attn_mma(
    const __nv_bfloat16* __restrict__ q, const __nv_bfloat16* __restrict__ k,
    const __nv_bfloat16* __restrict__ v, __nv_bfloat16* __restrict__ o,
    const float* __restrict__ Ac, const float* __restrict__ Bc)
{
    extern __shared__ __align__(16) char smd[];
    // Q 128x144B @0 (18432); stage s (0..2): K @18432+s*18432, V @+9216
    const uint32_t sb = smem_u32(smd);
    const int tid = threadIdx.x, w = tid >> 5, lam = tid & 31;
    const int by = blockIdx.y;
    const int b = by / NH, h = by % NH, kb = b >> 1;
    const int q0 = blockIdx.x * 128;

    const char* kg = (const char*)(k + ((size_t)kb * NS + (tid >> 2)) * NC + h * 64) + (tid & 3) * 32;
    const char* vg = (const char*)(v + ((size_t)kb * NS + (tid >> 2)) * NC + h * 64) + (tid & 3) * 32;
    const uint32_t ksb = sb + 18432 + (tid >> 2) * 144 + (tid & 3) * 32;
    const uint32_t vsb = ksb + 9216;
    const size_t kv_step = (size_t)64 * NC * 2;

    // prologue: KV tile0 (stage0), tile1 (stage1) first (overlaps with Q work)
    CP16(ksb, kg); CP16(ksb + 16, kg + 16);
    CP16(vsb, vg); CP16(vsb + 16, vg + 16);
    CP_COMMIT();
    CP16(ksb + 18432, kg + kv_step); CP16(ksb + 18432 + 16, kg + kv_step + 16);
    CP16(vsb + 18432, vg + kv_step); CP16(vsb + 18432 + 16, vg + kv_step + 16);
    CP_COMMIT();

    // Q stage with fused AdaIN affine (x*A + B), thread: row tid>>1, half tid&1
    {
        const int row = tid >> 1, half = tid & 1;
        const uint4* qsrc = (const uint4*)((const char*)(q + ((size_t)b * NS + q0 + row) * NC + h * 64) + half * 64);
        const float* Abp = Ac + b * NC + h * 64 + half * 32;
        const float* Bbp = Bc + b * NC + h * 64 + half * 32;
        char* qdst = smd + row * 144 + half * 64;
#pragma unroll
        for (int i = 0; i < 4; i++) {
            uint4 u = qsrc[i];
            float4 A0 = *(const float4*)(Abp + i * 8);
            float4 A1 = *(const float4*)(Abp + i * 8 + 4);
            float4 B0 = *(const float4*)(Bbp + i * 8);
            float4 B1 = *(const float4*)(Bbp + i * 8 + 4);
            uint16_t* e = (uint16_t*)&u;
            uint4 ov;
            ov.x = packbf(bf2f(e[0]) * A0.x + B0.x, bf2f(e[1]) * A0.y + B0.y);
            ov.y = packbf(bf2f(e[2]) * A0.z + B0.z, bf2f(e[3]) * A0.w + B0.w);
            ov.z = packbf(bf2f(e[4]) * A1.x + B1.x, bf2f(e[5]) * A1.y + B1.y);
            ov.w = packbf(bf2f(e[6]) * A1.z + B1.z, bf2f(e[7]) * A1.w + B1.w);
            *(uint4*)(qdst + i * 16) = ov;
        }
    }
    CP_WAIT1(); __syncthreads();

    uint32_t aq[4][4];
    {
        uint32_t qab = sb + (w * 16 + (lam & 15)) * 144 + (lam >> 4) * 16;
#pragma unroll
        for (int t = 0; t < 4; t++)
            ldm_x4(aq[t][0], aq[t][1], aq[t][2], aq[t][3], qab + t * 32);
    }

    float oacc[8][4];
#pragma unroll
    for (int j = 0; j < 8; j++)
#pragma unroll
        for (int e = 0; e < 4; e++) oacc[j][e] = 0.f;
    float l0 = 0.f, l1 = 0.f;

    const uint32_t kab0 = sb + 18432 + ((lam & 7) + ((lam >> 4) << 3)) * 144
                          + ((lam >> 3) & 1) * 16;
    const uint32_t vab0 = sb + 18432 + 9216 + (lam & 15) * 144 + (lam >> 4) * 16;

    int st = 0;          // stage of current tile i
    for (int i = 0; i < 32; i++) {
        // early prefetch: tile i+2 into free stage (consumed at i-1)
        const int pf = (st + 2 >= 3) ? st - 1 : st + 2;
        if (i + 2 < 32) {
            const char* kgi = kg + (size_t)(i + 2) * kv_step;
            const char* vgi = vg + (size_t)(i + 2) * kv_step;
            uint32_t ko = ksb + pf * 18432, vo = vsb + pf * 18432;
            CP16(ko, kgi); CP16(ko + 16, kgi + 16);
            CP16(vo, vgi); CP16(vo + 16, vgi + 16);
        }
        CP_COMMIT();

        const uint32_t kab = kab0 + st * 18432;
        const uint32_t vab = vab0 + st * 18432;

        // S = Q @ K^T : c[j] covers kv cols 8j..8j+7
        float c[8][4];
#pragma unroll
        for (int j = 0; j < 8; j++)
#pragma unroll
            for (int e = 0; e < 4; e++) c[j][e] = 0.f;
#pragma unroll
        for (int t = 0; t < 4; t++) {
#pragma unroll
            for (int jp = 0; jp < 4; jp++) {
                uint32_t b0, b1, b2, b3;
                ldm_x4(b0, b1, b2, b3, kab + jp * (16 * 144) + t * 32);
                mma_bf16(c[2 * jp],     aq[t], b0, b1);
                mma_bf16(c[2 * jp + 1], aq[t], b2, b3);
            }
        }
        float p0 = 0.f, p1 = 0.f;
#pragma unroll
        for (int j = 0; j < 8; j++) {
            c[j][0] = ex2f(c[j][0]); c[j][1] = ex2f(c[j][1]);
            c[j][2] = ex2f(c[j][2]); c[j][3] = ex2f(c[j][3]);
            p0 += c[j][0] + c[j][1];
            p1 += c[j][2] + c[j][3];
        }
        l0 += p0; l1 += p1;
        uint32_t ap[4][4];
#pragma unroll
        for (int t = 0; t < 4; t++) {
            ap[t][0] = packbf(c[2*t][0],   c[2*t][1]);
            ap[t][1] = packbf(c[2*t][2],   c[2*t][3]);
            ap[t][2] = packbf(c[2*t+1][0], c[2*t+1][1]);
            ap[t][3] = packbf(c[2*t+1][2], c[2*t+1][3]);
        }
#pragma unroll
        for (int t = 0; t < 4; t++) {
#pragma unroll
            for (int jp = 0; jp < 4; jp++) {
                uint32_t b0, b1, b2, b3;
                ldm_x4t(b0, b1, b2, b3, vab + t * (16 * 144) + jp * 32);
                mma_bf16(oacc[2 * jp],     ap[t], b0, b1);
                mma_bf16(oacc[2 * jp + 1], ap[t], b2, b3);
            }
        }
        CP_WAIT1(); __syncthreads();
        st = (st + 1 >= 3) ? 0 : st + 1;
    }

    l0 += __shfl_xor_sync(0xffffffffu, l0, 1);
    l0 += __shfl_xor_sync(0xffffffffu, l0, 2);
    l1 += __shfl_xor_sync(0xffffffffu, l1, 1);
    l1 += __shfl_xor_sync(0xffffffffu, l1, 2);
    const float i0 = 1.f / l0, i1 = 1.f / l1;

    const int r = q0 + w * 16 + (lam >> 2);
    __nv_bfloat16* ob0 = o + ((size_t)b * NS + r) * NC + h * 64 + 2 * (lam & 3);
#pragma unroll
    for (int j = 0; j < 8; j++) {
        *(uint32_t*)(ob0 + j * 8)          = packbf(oacc[j][0] * i0, oacc[j][1] * i0);
        *(uint32_t*)(ob0 + 8 * NC + j * 8) = packbf(oacc[j][2] * i1, oacc[j][3] * i1);
    }
}

// ---------------- launch ----------------
extern "C" void kernel_launch(void* const* d_in, const int* in_sizes, int n_in,
                              void* d_out, int out_size)
{
    const float* hs = (const float*)d_in[0];
    const float* wq = (const float*)d_in[1];
    const float* wk = (const float*)d_in[2];
    const float* wv = (const float*)d_in[3];
    const float* wo = (const float*)d_in[4];
    const float* bo = (const float*)d_in[5];
    float* out = (float*)d_out;

    __nv_bfloat16 *hsb, *wqb, *wkb, *wvb, *wob, *qb, *kbp, *vbp, *obp;
    float *ps, *pq, *Ac, *Bc;
    cudaGetSymbolAddress((void**)&hsb, g_hsb);
    cudaGetSymbolAddress((void**)&wqb, g_wqb);
    cudaGetSymbolAddress((void**)&wkb, g_wkb);
    cudaGetSymbolAddress((void**)&wvb, g_wvb);
    cudaGetSymbolAddress((void**)&wob, g_wob);
    cudaGetSymbolAddress((void**)&qb,  g_qb);
    cudaGetSymbolAddress((void**)&kbp, g_kb);
    cudaGetSymbolAddress((void**)&vbp, g_vb);
    cudaGetSymbolAddress((void**)&obp, g_ob);
    cudaGetSymbolAddress((void**)&ps,  g_ps);
    cudaGetSymbolAddress((void**)&pq,  g_pq);
    cudaGetSymbolAddress((void**)&Ac,  g_A);
    cudaGetSymbolAddress((void**)&Bc,  g_B);

    const int ATTN_SMEM = 18432 + 3 * 18432;   // 73728
    cudaFuncSetAttribute(attn_mma, cudaFuncAttributeMaxDynamicSharedMemorySize, ATTN_SMEM);

    // one merged convert (hs + 4 weights)
    conv_all<<<6720, 256>>>(hs, wq, wk, wv, wo, hsb, wqb, wkb, wvb, wob);

    // merged Q + K + V projections (K/V from source batches 0,2 only)
    gemm_mma<5><<<dim3(10, 64), 256>>>(hsb, wkb, wvb, wqb, nullptr, nullptr,
                                       nullptr, kbp, vbp, qb);

    // AdaIN stats (coalesced, full-chip) -> affine coeffs
    adain_p1<<<512, 320>>>(qb, ps, pq);
    adain_p2<<<10, 256>>>(ps, pq, Ac, Bc);

    // attention with fused AdaIN-apply on Q
    attn_mma<<<dim3(16, 40), 256, ATTN_SMEM>>>(qb, kbp, vbp, obp, Ac, Bc);

    // output projection + bias + residual (fp32)
    gemm_mma<2><<<dim3(5, 64), 256>>>(obp, wob, nullptr, nullptr, bo, hs,
                                      out, nullptr, nullptr, nullptr);
}

// round 7
// speedup vs baseline: 7.7143x; 1.0347x over previous
#include <cuda_runtime.h>
#include <cuda_bf16.h>
#include <math.h>
#include <stddef.h>
#include <stdint.h>

#define NB 4
#define NS 2048
#define NC 640
#define NH 10
#define ND 64

// log2(e) * attn_scale(0.125): folded into adain coeffs; softmax uses ex2
#define QSCALE 0.1803368801111204f

// ---------------- device scratch (no allocs allowed) ----------------
__device__ __nv_bfloat16 g_hsb[(size_t)NB * NS * NC];
__device__ __nv_bfloat16 g_wqb[NC * NC];
__device__ __nv_bfloat16 g_wkb[NC * NC];
__device__ __nv_bfloat16 g_wvb[NC * NC];
__device__ __nv_bfloat16 g_wob[NC * NC];
__device__ __nv_bfloat16 g_qb [(size_t)NB * NS * NC];   // q bf16 (raw projection)
__device__ __nv_bfloat16 g_kb [(size_t)2  * NS * NC];   // k bf16 (batches 0,2)
__device__ __nv_bfloat16 g_vb [(size_t)2  * NS * NC];
__device__ __nv_bfloat16 g_ob [(size_t)NB * NS * NC];   // attention out bf16
__device__ float g_ps[512 * NC];   // partial sums   (4 b x 128 chunks)
__device__ float g_pq[512 * NC];   // partial sq-sums
__device__ float g_A[NB * NC];     // per-(b,channel) affine scale (incl QSCALE)
__device__ float g_B[NB * NC];     // per-(b,channel) affine bias  (incl QSCALE)

// ---------------- PTX helpers (baseline sm_80+, safe on sm_100) ------------
__device__ __forceinline__ uint32_t smem_u32(const void* p) {
    uint32_t a;
    asm("{ .reg .u64 t; cvta.to.shared.u64 t, %1; cvt.u32.u64 %0, t; }" : "=r"(a) : "l"(p));
    return a;
}

#define CP16(dst, src) \
    asm volatile("cp.async.cg.shared.global [%0], [%1], 16;" :: "r"(dst), "l"(src))
#define CP_COMMIT() asm volatile("cp.async.commit_group;" ::: "memory")
#define CP_WAIT1()  asm volatile("cp.async.wait_group 1;" ::: "memory")

__device__ __forceinline__ void ldm_x4(uint32_t& r0, uint32_t& r1, uint32_t& r2, uint32_t& r3, uint32_t a) {
    asm volatile("ldmatrix.sync.aligned.m8n8.x4.shared.b16 {%0,%1,%2,%3}, [%4];"
        : "=r"(r0), "=r"(r1), "=r"(r2), "=r"(r3) : "r"(a));
}
__device__ __forceinline__ void ldm_x4t(uint32_t& r0, uint32_t& r1, uint32_t& r2, uint32_t& r3, uint32_t a) {
    asm volatile("ldmatrix.sync.aligned.m8n8.x4.trans.shared.b16 {%0,%1,%2,%3}, [%4];"
        : "=r"(r0), "=r"(r1), "=r"(r2), "=r"(r3) : "r"(a));
}
__device__ __forceinline__ void mma_bf16(float* c, const uint32_t* a,
                                         uint32_t b0, uint32_t b1) {
    asm volatile("mma.sync.aligned.m16n8k16.row.col.f32.bf16.bf16.f32 "
        "{%0,%1,%2,%3}, {%4,%5,%6,%7}, {%8,%9}, {%0,%1,%2,%3};"
        : "+f"(c[0]), "+f"(c[1]), "+f"(c[2]), "+f"(c[3])
        : "r"(a[0]), "r"(a[1]), "r"(a[2]), "r"(a[3]), "r"(b0), "r"(b1));
}
__device__ __forceinline__ uint32_t packbf(float lo, float hi) {
    __nv_bfloat162 p = __floats2bfloat162_rn(lo, hi);
    return *(uint32_t*)&p;
}
__device__ __forceinline__ float ex2f(float x) {
    float r;
    asm("ex2.approx.ftz.f32 %0, %1;" : "=f"(r) : "f"(x));
    return r;
}
__device__ __forceinline__ float bf2f(uint16_t u) {
    __nv_bfloat16 h = *(__nv_bfloat16*)&u;
    return __bfloat162float(h);
}

// ---------------- merged fp32 -> bf16 convert (hs + 4 weights) -------------
__global__ void __launch_bounds__(256) conv_all(
    const float* __restrict__ hs, const float* __restrict__ wq,
    const float* __restrict__ wk, const float* __restrict__ wv,
    const float* __restrict__ wo,
    __nv_bfloat16* __restrict__ hsb, __nv_bfloat16* __restrict__ wqb,
    __nv_bfloat16* __restrict__ wkb, __nv_bfloat16* __restrict__ wvb,
    __nv_bfloat16* __restrict__ wob)
{
    int blk = blockIdx.x;
    const float* src; __nv_bfloat16* dst; int base;
    if (blk < 5120) { src = hs; dst = hsb; base = blk; }
    else {
        int t = blk - 5120, w = t / 400;
        base = t % 400;
        src = (w == 0) ? wq : (w == 1) ? wk : (w == 2) ? wv : wo;
        dst = (w == 0) ? wqb : (w == 1) ? wkb : (w == 2) ? wvb : wob;
    }
    int i = base * 256 + threadIdx.x;
    float4 v = ((const float4*)src)[i];
    uint2 o;
    o.x = packbf(v.x, v.y);
    o.y = packbf(v.z, v.w);
    ((uint2*)dst)[i] = o;
}

// ---------------- GEMM: C[M,640] = A[M,640] @ W[640,640]^T ------------------
// MODE 2: fp32 out + bias + residual (final projection), grid (5, 64); W=Wk slot.
// MODE 5: merged QKV. grid (10, 64):
//   by <  32 : K/V path (rows remapped to source batches {0,2}):
//              bx<5 -> Wk/outK else Wv/outV; col0=(bx%5)*128; row0=by*128
//   by >= 32 : Q path: Wq/outQ; col0=(bx%5)*128; row0=((by-32)*2+(bx/5))*128
// 128x128 block, BK=32, 256 threads (8 warps, each 32x64), cp.async 2-stage.
template <int MODE>
__global__ void __launch_bounds__(256) gemm_mma(
    const __nv_bfloat16* __restrict__ Ain,
    const __nv_bfloat16* __restrict__ Wk, const __nv_bfloat16* __restrict__ Wv,
    const __nv_bfloat16* __restrict__ Wq,
    const float* __restrict__ bias, const float* __restrict__ resid,
    float* __restrict__ outF,
    __nv_bfloat16* __restrict__ outK, __nv_bfloat16* __restrict__ outV,
    __nv_bfloat16* __restrict__ outQ)
{
    __shared__ __align__(16) char smem[40960];   // 2 stages x (A 10240 + B 10240)
    const uint32_t sb = smem_u32(smem);
    const int tid = threadIdx.x;
    const int w = tid >> 5, lam = tid & 31;

    const __nv_bfloat16* W;
    __nv_bfloat16* outB = nullptr;
    int row0, col0;
    bool remap = false;
    if (MODE == 5) {
        int bx = blockIdx.x, by = blockIdx.y;
        col0 = (bx % 5) * 128;
        if (by < 32) {
            W = (bx < 5) ? Wk : Wv;
            outB = (bx < 5) ? outK : outV;
            row0 = by * 128;
            remap = true;
        } else {
            W = Wq; outB = outQ;
            row0 = ((by - 32) * 2 + (bx / 5)) * 128;
        }
    } else {
        W = Wk;
        row0 = blockIdx.y * 128; col0 = blockIdx.x * 128;
    }

    const int warp_m = (w & 3) * 32, warp_n = (w >> 2) * 64;

    const int lrow = tid >> 1;
    const int gr = row0 + lrow;
    const int arow = remap ? ((gr & 2047) + ((gr >> 11) << 12)) : gr;
    const char* ag = (const char*)(Ain + (size_t)arow * NC) + (tid & 1) * 32;
    const char* bg = (const char*)(W + (size_t)(col0 + lrow) * NC) + (tid & 1) * 32;
    const uint32_t asb = sb + lrow * 80 + (tid & 1) * 32;
    const uint32_t bsb = sb + 10240 + lrow * 80 + (tid & 1) * 32;

    float acc[2][8][4];
#pragma unroll
    for (int i = 0; i < 2; i++)
#pragma unroll
        for (int j = 0; j < 8; j++)
#pragma unroll
            for (int e = 0; e < 4; e++) acc[i][j][e] = 0.f;

#pragma unroll
    for (int s = 0; s < 2; s++) {
        uint32_t so = s * 20480;
        int kb_ = s * 64;
        CP16(asb + so, ag + kb_); CP16(asb + so + 16, ag + kb_ + 16);
        CP16(bsb + so, bg + kb_); CP16(bsb + so + 16, bg + kb_ + 16);
        CP_COMMIT();
    }

    for (int c = 0; c < 20; c++) {
        CP_WAIT1(); __syncthreads();
        const int st = c & 1;
        const uint32_t sa  = sb + st * 20480;
        const uint32_t sbm = sb + 10240 + st * 20480;
        const uint32_t aab = sa + (warp_m + (lam & 15)) * 80 + (lam >> 4) * 16;
        const uint32_t bab4 = sbm + (warp_n + (lam & 7) + ((lam >> 4) << 3)) * 80
                              + ((lam >> 3) & 1) * 16;
#pragma unroll
        for (int s = 0; s < 2; s++) {
            uint32_t a0[4], a1[4];
            ldm_x4(a0[0], a0[1], a0[2], a0[3], aab + s * 32);
            ldm_x4(a1[0], a1[1], a1[2], a1[3], aab + 16 * 80 + s * 32);
#pragma unroll
            for (int jp = 0; jp < 4; jp++) {
                uint32_t b0, b1, b2, b3;
                ldm_x4(b0, b1, b2, b3, bab4 + jp * (16 * 80) + s * 32);
                mma_bf16(acc[0][2 * jp],     a0, b0, b1);
                mma_bf16(acc[0][2 * jp + 1], a0, b2, b3);
                mma_bf16(acc[1][2 * jp],     a1, b0, b1);
                mma_bf16(acc[1][2 * jp + 1], a1, b2, b3);
            }
        }
        __syncthreads();
        if (c + 2 < 20) {
            uint32_t so = st * 20480;
            int kb_ = (c + 2) * 64;
            CP16(asb + so, ag + kb_); CP16(asb + so + 16, ag + kb_ + 16);
            CP16(bsb + so, bg + kb_); CP16(bsb + so + 16, bg + kb_ + 16);
        }
        CP_COMMIT();
    }

    const int rb = row0 + warp_m + (lam >> 2);
    const int cb = col0 + warp_n + 2 * (lam & 3);
#pragma unroll
    for (int im = 0; im < 2; im++) {
#pragma unroll
        for (int j = 0; j < 8; j++) {
            int r = rb + im * 16;
            int cc = cb + j * 8;
            float* a4 = acc[im][j];
            if (MODE == 2) {
                size_t o0 = (size_t)r * NC + cc;
                size_t o1 = (size_t)(r + 8) * NC + cc;
                float2 rv0 = *(const float2*)(resid + o0);
                float2 rv1 = *(const float2*)(resid + o1);
                float2 bv = *(const float2*)(bias + cc);
                *(float2*)(outF + o0) = make_float2(a4[0] + bv.x + rv0.x, a4[1] + bv.y + rv0.y);
                *(float2*)(outF + o1) = make_float2(a4[2] + bv.x + rv1.x, a4[3] + bv.y + rv1.y);
            } else {
                *(uint32_t*)(outB + (size_t)r * NC + cc) = packbf(a4[0], a4[1]);
                *(uint32_t*)(outB + (size_t)(r + 8) * NC + cc) = packbf(a4[2], a4[3]);
            }
        }
    }
}

// ------------- AdaIN stats pass 1: coalesced partial sums -------------------
// 512 blocks = 4 batches x 128 chunks of 16 rows. 320 threads: thread t owns
// columns 2t, 2t+1 (one uint32 = 2 bf16 per row). Fully coalesced rows.
__global__ void __launch_bounds__(320) adain_p1(
    const __nv_bfloat16* __restrict__ qb, float* __restrict__ ps, float* __restrict__ pq)
{
    const int blk = blockIdx.x;            // b = blk>>7, chunk = blk&127
    const int b = blk >> 7, ch = blk & 127;
    const uint32_t* p = (const uint32_t*)(qb + (((size_t)b * NS) + ch * 16) * NC) + threadIdx.x;
    float s0 = 0.f, s1 = 0.f, q0 = 0.f, q1 = 0.f;
#pragma unroll
    for (int r = 0; r < 16; r++) {
        uint32_t u = p[r * 320];
        __nv_bfloat162 h = *(__nv_bfloat162*)&u;
        float x0 = __bfloat162float(h.x), x1 = __bfloat162float(h.y);
        s0 += x0; q0 += x0 * x0;
        s1 += x1; q1 += x1 * x1;
    }
    *(float2*)(ps + blk * NC + 2 * threadIdx.x) = make_float2(s0, s1);
    *(float2*)(pq + blk * NC + 2 * threadIdx.x) = make_float2(q0, q1);
}

// ------------- AdaIN stats pass 2: warp-parallel finalize -> affine coeffs --
// One warp per (batch pair, 4-column group): 2 x 160 = 320 warps (40 blocks).
// Each lane strides the 128 chunks with float4 loads (src + own batches),
// 16 shuffle reductions, lane 0 writes A/B for both batches.
// A = QSCALE * sd_src/sd_own, B = QSCALE*(m_src - m_own*sd_src/sd_own);
// even batches identity (A = QSCALE, B = 0).
__global__ void __launch_bounds__(256) adain_p2(
    const float* __restrict__ ps, const float* __restrict__ pq,
    float* __restrict__ Ac, float* __restrict__ Bc)
{
    const int wg   = (blockIdx.x << 3) | (threadIdx.x >> 5);   // 0..319
    const int lane = threadIdx.x & 31;
    const int pair = wg / 160;                 // 0..1
    const int c4   = (wg % 160) * 4;
    const int bs = pair * 2, bo = bs + 1;

    float acc[16];
#pragma unroll
    for (int e = 0; e < 16; e++) acc[e] = 0.f;

#pragma unroll
    for (int t = 0; t < 4; t++) {
        int j = lane + t * 32;
        float4 v;
        v = *(const float4*)(ps + (size_t)(bs * 128 + j) * NC + c4);
        acc[0] += v.x; acc[1] += v.y; acc[2] += v.z; acc[3] += v.w;
        v = *(const float4*)(pq + (size_t)(bs * 128 + j) * NC + c4);
        acc[4] += v.x; acc[5] += v.y; acc[6] += v.z; acc[7] += v.w;
        v = *(const float4*)(ps + (size_t)(bo * 128 + j) * NC + c4);
        acc[8] += v.x; acc[9] += v.y; acc[10] += v.z; acc[11] += v.w;
        v = *(const float4*)(pq + (size_t)(bo * 128 + j) * NC + c4);
        acc[12] += v.x; acc[13] += v.y; acc[14] += v.z; acc[15] += v.w;
    }
#pragma unroll
    for (int off = 16; off; off >>= 1)
#pragma unroll
        for (int e = 0; e < 16; e++)
            acc[e] += __shfl_xor_sync(0xffffffffu, acc[e], off);

    if (lane == 0) {
#pragma unroll
        for (int e = 0; e < 4; e++) {
            float Ssrc = acc[e], Qsrc = acc[4 + e];
            float Sown = acc[8 + e], Qown = acc[12 + e];
            float ms   = Ssrc / (float)NS;
            float vs   = (Qsrc - Ssrc * ms) / (float)(NS - 1);
            float sds  = sqrtf(vs + 1e-5f);
            float mo   = Sown / (float)NS;
            float vo   = (Qown - Sown * mo) / (float)(NS - 1);
            float sdo  = sqrtf(vo + 1e-5f);
            float r = sds / sdo;
            Ac[bs * NC + c4 + e] = QSCALE;
            Bc[bs * NC + c4 + e] = 0.f;
            Ac[bo * NC + c4 + e] = QSCALE * r;
            Bc[bo * NC + c4 + e] = QSCALE * (ms - mo * r);
        }
    }
}

// ---------------- Flash attention via mma.sync ------------------------------
// Block: 128 q-rows of one (b,h), 256 threads (8 warps x 16 rows). BK=64.
// AdaIN-apply fused into Q smem staging (affine coeffs from adain_p2).
// 3-stage cp.async KV pipeline with early prefetch. No-max base-2 softmax.
__global__ void __launch_bounds__(256, 2) attn_mma(
    const __nv_bfloat16* __restrict__ q, const __nv_bfloat16* __restrict__ k,
    const __nv_bfloat16* __restrict__ v, __nv_bfloat16* __restrict__ o,
    const float* __restrict__ Ac, const float* __restrict__ Bc)
{
    extern __shared__ __align__(16) char smd[];
    // Q 128x144B @0 (18432); stage s (0..2): K @18432+s*18432, V @+9216
    const uint32_t sb = smem_u32(smd);
    const int tid = threadIdx.x, w = tid >> 5, lam = tid & 31;
    const int by = blockIdx.y;
    const int b = by / NH, h = by % NH, kb = b >> 1;
    const int q0 = blockIdx.x * 128;

    const char* kg = (const char*)(k + ((size_t)kb * NS + (tid >> 2)) * NC + h * 64) + (tid & 3) * 32;
    const char* vg = (const char*)(v + ((size_t)kb * NS + (tid >> 2)) * NC + h * 64) + (tid & 3) * 32;
    const uint32_t ksb = sb + 18432 + (tid >> 2) * 144 + (tid & 3) * 32;
    const uint32_t vsb = ksb + 9216;
    const size_t kv_step = (size_t)64 * NC * 2;

    // prologue: KV tile0 (stage0), tile1 (stage1) first (overlaps with Q work)
    CP16(ksb, kg); CP16(ksb + 16, kg + 16);
    CP16(vsb, vg); CP16(vsb + 16, vg + 16);
    CP_COMMIT();
    CP16(ksb + 18432, kg + kv_step); CP16(ksb + 18432 + 16, kg + kv_step + 16);
    CP16(vsb + 18432, vg + kv_step); CP16(vsb + 18432 + 16, vg + kv_step + 16);
    CP_COMMIT();

    // Q stage with fused AdaIN affine (x*A + B), thread: row tid>>1, half tid&1
    {
        const int row = tid >> 1, half = tid & 1;
        const uint4* qsrc = (const uint4*)((const char*)(q + ((size_t)b * NS + q0 + row) * NC + h * 64) + half * 64);
        const float* Abp = Ac + b * NC + h * 64 + half * 32;
        const float* Bbp = Bc + b * NC + h * 64 + half * 32;
        char* qdst = smd + row * 144 + half * 64;
#pragma unroll
        for (int i = 0; i < 4; i++) {
            uint4 u = qsrc[i];
            float4 A0 = *(const float4*)(Abp + i * 8);
            float4 A1 = *(const float4*)(Abp + i * 8 + 4);
            float4 B0 = *(const float4*)(Bbp + i * 8);
            float4 B1 = *(const float4*)(Bbp + i * 8 + 4);
            uint16_t* e = (uint16_t*)&u;
            uint4 ov;
            ov.x = packbf(bf2f(e[0]) * A0.x + B0.x, bf2f(e[1]) * A0.y + B0.y);
            ov.y = packbf(bf2f(e[2]) * A0.z + B0.z, bf2f(e[3]) * A0.w + B0.w);
            ov.z = packbf(bf2f(e[4]) * A1.x + B1.x, bf2f(e[5]) * A1.y + B1.y);
            ov.w = packbf(bf2f(e[6]) * A1.z + B1.z, bf2f(e[7]) * A1.w + B1.w);
            *(uint4*)(qdst + i * 16) = ov;
        }
    }
    CP_WAIT1(); __syncthreads();

    uint32_t aq[4][4];
    {
        uint32_t qab = sb + (w * 16 + (lam & 15)) * 144 + (lam >> 4) * 16;
#pragma unroll
        for (int t = 0; t < 4; t++)
            ldm_x4(aq[t][0], aq[t][1], aq[t][2], aq[t][3], qab + t * 32);
    }

    float oacc[8][4];
#pragma unroll
    for (int j = 0; j < 8; j++)
#pragma unroll
        for (int e = 0; e < 4; e++) oacc[j][e] = 0.f;
    float l0 = 0.f, l1 = 0.f;

    const uint32_t kab0 = sb + 18432 + ((lam & 7) + ((lam >> 4) << 3)) * 144
                          + ((lam >> 3) & 1) * 16;
    const uint32_t vab0 = sb + 18432 + 9216 + (lam & 15) * 144 + (lam >> 4) * 16;

    int st = 0;          // stage of current tile i
    for (int i = 0; i < 32; i++) {
        // early prefetch: tile i+2 into free stage (consumed at i-1)
        const int pf = (st + 2 >= 3) ? st - 1 : st + 2;
        if (i + 2 < 32) {
            const char* kgi = kg + (size_t)(i + 2) * kv_step;
            const char* vgi = vg + (size_t)(i + 2) * kv_step;
            uint32_t ko = ksb + pf * 18432, vo = vsb + pf * 18432;
            CP16(ko, kgi); CP16(ko + 16, kgi + 16);
            CP16(vo, vgi); CP16(vo + 16, vgi + 16);
        }
        CP_COMMIT();

        const uint32_t kab = kab0 + st * 18432;
        const uint32_t vab = vab0 + st * 18432;

        // S = Q @ K^T : c[j] covers kv cols 8j..8j+7
        float c[8][4];
#pragma unroll
        for (int j = 0; j < 8; j++)
#pragma unroll
            for (int e = 0; e < 4; e++) c[j][e] = 0.f;
#pragma unroll
        for (int t = 0; t < 4; t++) {
#pragma unroll
            for (int jp = 0; jp < 4; jp++) {
                uint32_t b0, b1, b2, b3;
                ldm_x4(b0, b1, b2, b3, kab + jp * (16 * 144) + t * 32);
                mma_bf16(c[2 * jp],     aq[t], b0, b1);
                mma_bf16(c[2 * jp + 1], aq[t], b2, b3);
            }
        }
        float p0 = 0.f, p1 = 0.f;
#pragma unroll
        for (int j = 0; j < 8; j++) {
            c[j][0] = ex2f(c[j][0]); c[j][1] = ex2f(c[j][1]);
            c[j][2] = ex2f(c[j][2]); c[j][3] = ex2f(c[j][3]);
            p0 += c[j][0] + c[j][1];
            p1 += c[j][2] + c[j][3];
        }
        l0 += p0; l1 += p1;
        uint32_t ap[4][4];
#pragma unroll
        for (int t = 0; t < 4; t++) {
            ap[t][0] = packbf(c[2*t][0],   c[2*t][1]);
            ap[t][1] = packbf(c[2*t][2],   c[2*t][3]);
            ap[t][2] = packbf(c[2*t+1][0], c[2*t+1][1]);
            ap[t][3] = packbf(c[2*t+1][2], c[2*t+1][3]);
        }
#pragma unroll
        for (int t = 0; t < 4; t++) {
#pragma unroll
            for (int jp = 0; jp < 4; jp++) {
                uint32_t b0, b1, b2, b3;
                ldm_x4t(b0, b1, b2, b3, vab + t * (16 * 144) + jp * 32);
                mma_bf16(oacc[2 * jp],     ap[t], b0, b1);
                mma_bf16(oacc[2 * jp + 1], ap[t], b2, b3);
            }
        }
        CP_WAIT1(); __syncthreads();
        st = (st + 1 >= 3) ? 0 : st + 1;
    }

    l0 += __shfl_xor_sync(0xffffffffu, l0, 1);
    l0 += __shfl_xor_sync(0xffffffffu, l0, 2);
    l1 += __shfl_xor_sync(0xffffffffu, l1, 1);
    l1 += __shfl_xor_sync(0xffffffffu, l1, 2);
    const float i0 = 1.f / l0, i1 = 1.f / l1;

    const int r = q0 + w * 16 + (lam >> 2);
    __nv_bfloat16* ob0 = o + ((size_t)b * NS + r) * NC + h * 64 + 2 * (lam & 3);
#pragma unroll
    for (int j = 0; j < 8; j++) {
        *(uint32_t*)(ob0 + j * 8)          = packbf(oacc[j][0] * i0, oacc[j][1] * i0);
        *(uint32_t*)(ob0 + 8 * NC + j * 8) = packbf(oacc[j][2] * i1, oacc[j][3] * i1);
    }
}

// ---------------- launch ----------------
extern "C" void kernel_launch(void* const* d_in, const int* in_sizes, int n_in,
                              void* d_out, int out_size)
{
    const float* hs = (const float*)d_in[0];
    const float* wq = (const float*)d_in[1];
    const float* wk = (const float*)d_in[2];
    const float* wv = (const float*)d_in[3];
    const float* wo = (const float*)d_in[4];
    const float* bo = (const float*)d_in[5];
    float* out = (float*)d_out;

    __nv_bfloat16 *hsb, *wqb, *wkb, *wvb, *wob, *qb, *kbp, *vbp, *obp;
    float *ps, *pq, *Ac, *Bc;
    cudaGetSymbolAddress((void**)&hsb, g_hsb);
    cudaGetSymbolAddress((void**)&wqb, g_wqb);
    cudaGetSymbolAddress((void**)&wkb, g_wkb);
    cudaGetSymbolAddress((void**)&wvb, g_wvb);
    cudaGetSymbolAddress((void**)&wob, g_wob);
    cudaGetSymbolAddress((void**)&qb,  g_qb);
    cudaGetSymbolAddress((void**)&kbp, g_kb);
    cudaGetSymbolAddress((void**)&vbp, g_vb);
    cudaGetSymbolAddress((void**)&obp, g_ob);
    cudaGetSymbolAddress((void**)&ps,  g_ps);
    cudaGetSymbolAddress((void**)&pq,  g_pq);
    cudaGetSymbolAddress((void**)&Ac,  g_A);
    cudaGetSymbolAddress((void**)&Bc,  g_B);

    const int ATTN_SMEM = 18432 + 3 * 18432;   // 73728
    cudaFuncSetAttribute(attn_mma, cudaFuncAttributeMaxDynamicSharedMemorySize, ATTN_SMEM);

    // one merged convert (hs + 4 weights)
    conv_all<<<6720, 256>>>(hs, wq, wk, wv, wo, hsb, wqb, wkb, wvb, wob);

    // merged Q + K + V projections (K/V from source batches 0,2 only)
    gemm_mma<5><<<dim3(10, 64), 256>>>(hsb, wkb, wvb, wqb, nullptr, nullptr,
                                       nullptr, kbp, vbp, qb);

    // AdaIN stats (coalesced p1, warp-parallel p2) -> affine coeffs
    adain_p1<<<512, 320>>>(qb, ps, pq);
    adain_p2<<<40, 256>>>(ps, pq, Ac, Bc);

    // attention with fused AdaIN-apply on Q
    attn_mma<<<dim3(16, 40), 256, ATTN_SMEM>>>(qb, kbp, vbp, obp, Ac, Bc);

    // output projection + bias + residual (fp32)
    gemm_mma<2><<<dim3(5, 64), 256>>>(obp, wob, nullptr, nullptr, bo, hs,
                                      out, nullptr, nullptr, nullptr);
}

// round 8
// speedup vs baseline: 7.8349x; 1.0156x over previous
#include <cuda_runtime.h>
#include <cuda_bf16.h>
#include <math.h>
#include <stddef.h>
#include <stdint.h>

#define NB 4
#define NS 2048
#define NC 640
#define NH 10
#define ND 64

// log2(e) * attn_scale(0.125): folded into adain coeffs; softmax uses ex2
#define QSCALE 0.1803368801111204f

// ---------------- device scratch (no allocs allowed) ----------------
__device__ __nv_bfloat16 g_hsb[(size_t)NB * NS * NC];
__device__ __nv_bfloat16 g_wqb[NC * NC];
__device__ __nv_bfloat16 g_wkb[NC * NC];
__device__ __nv_bfloat16 g_wvb[NC * NC];
__device__ __nv_bfloat16 g_wob[NC * NC];
__device__ __nv_bfloat16 g_qb [(size_t)NB * NS * NC];   // q bf16 (raw projection)
__device__ __nv_bfloat16 g_kb [(size_t)2  * NS * NC];   // k bf16 (batches 0,2)
__device__ __nv_bfloat16 g_vb [(size_t)2  * NS * NC];
__device__ __nv_bfloat16 g_ob [(size_t)NB * NS * NC];   // attention out bf16
__device__ float g_ps[64 * NC];    // partial sums   (4 b x 16 chunks of 128 rows)
__device__ float g_pq[64 * NC];    // partial sq-sums
__device__ float g_A[NB * NC];     // per-(b,channel) affine scale (incl QSCALE)
__device__ float g_B[NB * NC];     // per-(b,channel) affine bias  (incl QSCALE)

// ---------------- PTX helpers (baseline sm_80+, safe on sm_100) ------------
__device__ __forceinline__ uint32_t smem_u32(const void* p) {
    uint32_t a;
    asm("{ .reg .u64 t; cvta.to.shared.u64 t, %1; cvt.u32.u64 %0, t; }" : "=r"(a) : "l"(p));
    return a;
}

#define CP16(dst, src) \
    asm volatile("cp.async.cg.shared.global [%0], [%1], 16;" :: "r"(dst), "l"(src))
#define CP_COMMIT() asm volatile("cp.async.commit_group;" ::: "memory")
#define CP_WAIT1()  asm volatile("cp.async.wait_group 1;" ::: "memory")

__device__ __forceinline__ void ldm_x4(uint32_t& r0, uint32_t& r1, uint32_t& r2, uint32_t& r3, uint32_t a) {
    asm volatile("ldmatrix.sync.aligned.m8n8.x4.shared.b16 {%0,%1,%2,%3}, [%4];"
        : "=r"(r0), "=r"(r1), "=r"(r2), "=r"(r3) : "r"(a));
}
__device__ __forceinline__ void ldm_x4t(uint32_t& r0, uint32_t& r1, uint32_t& r2, uint32_t& r3, uint32_t a) {
    asm volatile("ldmatrix.sync.aligned.m8n8.x4.trans.shared.b16 {%0,%1,%2,%3}, [%4];"
        : "=r"(r0), "=r"(r1), "=r"(r2), "=r"(r3) : "r"(a));
}
__device__ __forceinline__ void mma_bf16(float* c, const uint32_t* a,
                                         uint32_t b0, uint32_t b1) {
    asm volatile("mma.sync.aligned.m16n8k16.row.col.f32.bf16.bf16.f32 "
        "{%0,%1,%2,%3}, {%4,%5,%6,%7}, {%8,%9}, {%0,%1,%2,%3};"
        : "+f"(c[0]), "+f"(c[1]), "+f"(c[2]), "+f"(c[3])
        : "r"(a[0]), "r"(a[1]), "r"(a[2]), "r"(a[3]), "r"(b0), "r"(b1));
}
__device__ __forceinline__ uint32_t packbf(float lo, float hi) {
    __nv_bfloat162 p = __floats2bfloat162_rn(lo, hi);
    return *(uint32_t*)&p;
}
__device__ __forceinline__ float ex2f(float x) {
    float r;
    asm("ex2.approx.ftz.f32 %0, %1;" : "=f"(r) : "f"(x));
    return r;
}
__device__ __forceinline__ float bf2f(uint16_t u) {
    __nv_bfloat16 h = *(__nv_bfloat16*)&u;
    return __bfloat162float(h);
}

// ---------------- merged fp32 -> bf16 convert (hs + 4 weights) -------------
__global__ void __launch_bounds__(256) conv_all(
    const float* __restrict__ hs, const float* __restrict__ wq,
    const float* __restrict__ wk, const float* __restrict__ wv,
    const float* __restrict__ wo,
    __nv_bfloat16* __restrict__ hsb, __nv_bfloat16* __restrict__ wqb,
    __nv_bfloat16* __restrict__ wkb, __nv_bfloat16* __restrict__ wvb,
    __nv_bfloat16* __restrict__ wob)
{
    int blk = blockIdx.x;
    const float* src; __nv_bfloat16* dst; int base;
    if (blk < 5120) { src = hs; dst = hsb; base = blk; }
    else {
        int t = blk - 5120, w = t / 400;
        base = t % 400;
        src = (w == 0) ? wq : (w == 1) ? wk : (w == 2) ? wv : wo;
        dst = (w == 0) ? wqb : (w == 1) ? wkb : (w == 2) ? wvb : wob;
    }
    int i = base * 256 + threadIdx.x;
    float4 v = ((const float4*)src)[i];
    uint2 o;
    o.x = packbf(v.x, v.y);
    o.y = packbf(v.z, v.w);
    ((uint2*)dst)[i] = o;
}

// ---------------- GEMM: C[M,640] = A[M,640] @ W[640,640]^T ------------------
// MODE 2: fp32 out + bias + residual (final projection), grid (5, 64); W=Wk slot.
// MODE 5: merged QKV. grid (10, 64):
//   by <  32 : K/V path (rows remapped to source batches {0,2}):
//              bx<5 -> Wk/outK else Wv/outV; col0=(bx%5)*128; row0=by*128
//   by >= 32 : Q path: Wq/outQ; col0=(bx%5)*128; row0=((by-32)*2+(bx/5))*128
//              + fused AdaIN stats pass 1: per-block column sums/sq-sums of the
//              fp32 tile -> g_ps/g_pq[(row0>>7)*NC + col0 + c]
// 128x128 block, BK=32, 256 threads (8 warps, each 32x64), cp.async 2-stage.
template <int MODE>
__global__ void __launch_bounds__(256) gemm_mma(
    const __nv_bfloat16* __restrict__ Ain,
    const __nv_bfloat16* __restrict__ Wk, const __nv_bfloat16* __restrict__ Wv,
    const __nv_bfloat16* __restrict__ Wq,
    const float* __restrict__ bias, const float* __restrict__ resid,
    float* __restrict__ outF,
    __nv_bfloat16* __restrict__ outK, __nv_bfloat16* __restrict__ outV,
    __nv_bfloat16* __restrict__ outQ,
    float* __restrict__ ps, float* __restrict__ pq)
{
    __shared__ __align__(16) char smem[40960];   // 2 stages x (A 10240 + B 10240)
    const uint32_t sb = smem_u32(smem);
    const int tid = threadIdx.x;
    const int w = tid >> 5, lam = tid & 31;

    const __nv_bfloat16* W;
    __nv_bfloat16* outB = nullptr;
    int row0, col0;
    bool remap = false, qpath = false;
    if (MODE == 5) {
        int bx = blockIdx.x, by = blockIdx.y;
        col0 = (bx % 5) * 128;
        if (by < 32) {
            W = (bx < 5) ? Wk : Wv;
            outB = (bx < 5) ? outK : outV;
            row0 = by * 128;
            remap = true;
        } else {
            W = Wq; outB = outQ;
            row0 = ((by - 32) * 2 + (bx / 5)) * 128;
            qpath = true;
        }
    } else {
        W = Wk;
        row0 = blockIdx.y * 128; col0 = blockIdx.x * 128;
    }

    const int warp_m = (w & 3) * 32, warp_n = (w >> 2) * 64;

    const int lrow = tid >> 1;
    const int gr = row0 + lrow;
    const int arow = remap ? ((gr & 2047) + ((gr >> 11) << 12)) : gr;
    const char* ag = (const char*)(Ain + (size_t)arow * NC) + (tid & 1) * 32;
    const char* bg = (const char*)(W + (size_t)(col0 + lrow) * NC) + (tid & 1) * 32;
    const uint32_t asb = sb + lrow * 80 + (tid & 1) * 32;
    const uint32_t bsb = sb + 10240 + lrow * 80 + (tid & 1) * 32;

    float acc[2][8][4];
#pragma unroll
    for (int i = 0; i < 2; i++)
#pragma unroll
        for (int j = 0; j < 8; j++)
#pragma unroll
            for (int e = 0; e < 4; e++) acc[i][j][e] = 0.f;

#pragma unroll
    for (int s = 0; s < 2; s++) {
        uint32_t so = s * 20480;
        int kb_ = s * 64;
        CP16(asb + so, ag + kb_); CP16(asb + so + 16, ag + kb_ + 16);
        CP16(bsb + so, bg + kb_); CP16(bsb + so + 16, bg + kb_ + 16);
        CP_COMMIT();
    }

    for (int c = 0; c < 20; c++) {
        CP_WAIT1(); __syncthreads();
        const int st = c & 1;
        const uint32_t sa  = sb + st * 20480;
        const uint32_t sbm = sb + 10240 + st * 20480;
        const uint32_t aab = sa + (warp_m + (lam & 15)) * 80 + (lam >> 4) * 16;
        const uint32_t bab4 = sbm + (warp_n + (lam & 7) + ((lam >> 4) << 3)) * 80
                              + ((lam >> 3) & 1) * 16;
#pragma unroll
        for (int s = 0; s < 2; s++) {
            uint32_t a0[4], a1[4];
            ldm_x4(a0[0], a0[1], a0[2], a0[3], aab + s * 32);
            ldm_x4(a1[0], a1[1], a1[2], a1[3], aab + 16 * 80 + s * 32);
#pragma unroll
            for (int jp = 0; jp < 4; jp++) {
                uint32_t b0, b1, b2, b3;
                ldm_x4(b0, b1, b2, b3, bab4 + jp * (16 * 80) + s * 32);
                mma_bf16(acc[0][2 * jp],     a0, b0, b1);
                mma_bf16(acc[0][2 * jp + 1], a0, b2, b3);
                mma_bf16(acc[1][2 * jp],     a1, b0, b1);
                mma_bf16(acc[1][2 * jp + 1], a1, b2, b3);
            }
        }
        __syncthreads();
        if (c + 2 < 20) {
            uint32_t so = st * 20480;
            int kb_ = (c + 2) * 64;
            CP16(asb + so, ag + kb_); CP16(asb + so + 16, ag + kb_ + 16);
            CP16(bsb + so, bg + kb_); CP16(bsb + so + 16, bg + kb_ + 16);
        }
        CP_COMMIT();
    }

    const int rb = row0 + warp_m + (lam >> 2);
    const int cb = col0 + warp_n + 2 * (lam & 3);
#pragma unroll
    for (int im = 0; im < 2; im++) {
#pragma unroll
        for (int j = 0; j < 8; j++) {
            int r = rb + im * 16;
            int cc = cb + j * 8;
            float* a4 = acc[im][j];
            if (MODE == 2) {
                size_t o0 = (size_t)r * NC + cc;
                size_t o1 = (size_t)(r + 8) * NC + cc;
                float2 rv0 = *(const float2*)(resid + o0);
                float2 rv1 = *(const float2*)(resid + o1);
                float2 bv = *(const float2*)(bias + cc);
                *(float2*)(outF + o0) = make_float2(a4[0] + bv.x + rv0.x, a4[1] + bv.y + rv0.y);
                *(float2*)(outF + o1) = make_float2(a4[2] + bv.x + rv1.x, a4[3] + bv.y + rv1.y);
            } else {
                *(uint32_t*)(outB + (size_t)r * NC + cc) = packbf(a4[0], a4[1]);
                *(uint32_t*)(outB + (size_t)(r + 8) * NC + cc) = packbf(a4[2], a4[3]);
            }
        }
    }

    // ---- fused AdaIN stats pass 1 (Q path only) ----
    if (MODE == 5 && qpath) {
        float cs[16], cq[16];
#pragma unroll
        for (int j = 0; j < 8; j++) {
            float slo = 0.f, shi = 0.f, qlo = 0.f, qhi = 0.f;
#pragma unroll
            for (int im = 0; im < 2; im++) {
                float a0 = acc[im][j][0], a1 = acc[im][j][1];
                float a2 = acc[im][j][2], a3 = acc[im][j][3];
                slo += a0 + a2;           shi += a1 + a3;
                qlo += a0 * a0 + a2 * a2; qhi += a1 * a1 + a3 * a3;
            }
            // reduce across the 8 row-groups (lane strides 4, 8, 16)
#pragma unroll
            for (int off = 4; off < 32; off <<= 1) {
                slo += __shfl_xor_sync(0xffffffffu, slo, off);
                shi += __shfl_xor_sync(0xffffffffu, shi, off);
                qlo += __shfl_xor_sync(0xffffffffu, qlo, off);
                qhi += __shfl_xor_sync(0xffffffffu, qhi, off);
            }
            cs[2 * j] = slo; cs[2 * j + 1] = shi;
            cq[2 * j] = qlo; cq[2 * j + 1] = qhi;
        }
        // overlay reduction buffers on stage-0 A-tile (dead after chunk 18;
        // chunk-19 reads hit stage 1 @20480+, disjoint from [0, 4096))
        float* sS = (float*)smem;            // [4][128]
        float* sQ = (float*)(smem + 2048);   // [4][128]
        if (lam < 4) {
#pragma unroll
            for (int j = 0; j < 8; j++) {
                int cidx = warp_n + j * 8 + 2 * lam;
                sS[(w & 3) * 128 + cidx]     = cs[2 * j];
                sS[(w & 3) * 128 + cidx + 1] = cs[2 * j + 1];
                sQ[(w & 3) * 128 + cidx]     = cq[2 * j];
                sQ[(w & 3) * 128 + cidx + 1] = cq[2 * j + 1];
            }
        }
        __syncthreads();
        if (tid < 128) {
            float S = sS[tid] + sS[128 + tid] + sS[256 + tid] + sS[384 + tid];
            float Q = sQ[tid] + sQ[128 + tid] + sQ[256 + tid] + sQ[384 + tid];
            int chunk = row0 >> 7;           // 0..63
            ps[chunk * NC + col0 + tid] = S;
            pq[chunk * NC + col0 + tid] = Q;
        }
    }
}

// ------------- AdaIN stats pass 2: warp-parallel finalize -> affine coeffs --
// One warp per (batch pair, 4-column group): 2 x 160 = 320 warps (40 blocks).
// Lanes 0-15 load the 16 chunk-partials (float4 for 4 cols; src + own batch),
// shuffle-reduce, lane 0 writes A/B for both batches.
// A = QSCALE * sd_src/sd_own, B = QSCALE*(m_src - m_own*sd_src/sd_own);
// even batches identity (A = QSCALE, B = 0).
__global__ void __launch_bounds__(256) adain_p2(
    const float* __restrict__ ps, const float* __restrict__ pq,
    float* __restrict__ Ac, float* __restrict__ Bc)
{
    const int wg   = (blockIdx.x << 3) | (threadIdx.x >> 5);   // 0..319
    const int lane = threadIdx.x & 31;
    const int pair = wg / 160;                 // 0..1
    const int c4   = (wg % 160) * 4;
    const int bs = pair * 2, bo = bs + 1;

    float acc[16];
#pragma unroll
    for (int e = 0; e < 16; e++) acc[e] = 0.f;

    if (lane < 16) {
        int j = lane;                          // chunk within batch (16 per batch)
        float4 v;
        v = *(const float4*)(ps + (size_t)(bs * 16 + j) * NC + c4);
        acc[0] = v.x; acc[1] = v.y; acc[2] = v.z; acc[3] = v.w;
        v = *(const float4*)(pq + (size_t)(bs * 16 + j) * NC + c4);
        acc[4] = v.x; acc[5] = v.y; acc[6] = v.z; acc[7] = v.w;
        v = *(const float4*)(ps + (size_t)(bo * 16 + j) * NC + c4);
        acc[8] = v.x; acc[9] = v.y; acc[10] = v.z; acc[11] = v.w;
        v = *(const float4*)(pq + (size_t)(bo * 16 + j) * NC + c4);
        acc[12] = v.x; acc[13] = v.y; acc[14] = v.z; acc[15] = v.w;
    }
#pragma unroll
    for (int off = 16; off; off >>= 1)
#pragma unroll
        for (int e = 0; e < 16; e++)
            acc[e] += __shfl_xor_sync(0xffffffffu, acc[e], off);

    if (lane == 0) {
#pragma unroll
        for (int e = 0; e < 4; e++) {
            float Ssrc = acc[e], Qsrc = acc[4 + e];
            float Sown = acc[8 + e], Qown = acc[12 + e];
            float ms   = Ssrc / (float)NS;
            float vs   = (Qsrc - Ssrc * ms) / (float)(NS - 1);
            float sds  = sqrtf(vs + 1e-5f);
            float mo   = Sown / (float)NS;
            float vo   = (Qown - Sown * mo) / (float)(NS - 1);
            float sdo  = sqrtf(vo + 1e-5f);
            float r = sds / sdo;
            Ac[bs * NC + c4 + e] = QSCALE;
            Bc[bs * NC + c4 + e] = 0.f;
            Ac[bo * NC + c4 + e] = QSCALE * r;
            Bc[bo * NC + c4 + e] = QSCALE * (ms - mo * r);
        }
    }
}

// ---------------- Flash attention via mma.sync ------------------------------
// Block: 128 q-rows of one (b,h), 256 threads (8 warps x 16 rows). BK=64.
// AdaIN-apply fused into Q smem staging (affine coeffs from adain_p2).
// 3-stage cp.async KV pipeline with early prefetch. No-max base-2 softmax.
__global__ void __launch_bounds__(256, 2) attn_mma(
    const __nv_bfloat16* __restrict__ q, const __nv_bfloat16* __restrict__ k,
    const __nv_bfloat16* __restrict__ v, __nv_bfloat16* __restrict__ o,
    const float* __restrict__ Ac, const float* __restrict__ Bc)
{
    extern __shared__ __align__(16) char smd[];
    // Q 128x144B @0 (18432); stage s (0..2): K @18432+s*18432, V @+9216
    const uint32_t sb = smem_u32(smd);
    const int tid = threadIdx.x, w = tid >> 5, lam = tid & 31;
    const int by = blockIdx.y;
    const int b = by / NH, h = by % NH, kb = b >> 1;
    const int q0 = blockIdx.x * 128;

    const char* kg = (const char*)(k + ((size_t)kb * NS + (tid >> 2)) * NC + h * 64) + (tid & 3) * 32;
    const char* vg = (const char*)(v + ((size_t)kb * NS + (tid >> 2)) * NC + h * 64) + (tid & 3) * 32;
    const uint32_t ksb = sb + 18432 + (tid >> 2) * 144 + (tid & 3) * 32;
    const uint32_t vsb = ksb + 9216;
    const size_t kv_step = (size_t)64 * NC * 2;

    // prologue: KV tile0 (stage0), tile1 (stage1) first (overlaps with Q work)
    CP16(ksb, kg); CP16(ksb + 16, kg + 16);
    CP16(vsb, vg); CP16(vsb + 16, vg + 16);
    CP_COMMIT();
    CP16(ksb + 18432, kg + kv_step); CP16(ksb + 18432 + 16, kg + kv_step + 16);
    CP16(vsb + 18432, vg + kv_step); CP16(vsb + 18432 + 16, vg + kv_step + 16);
    CP_COMMIT();

    // Q stage with fused AdaIN affine (x*A + B), thread: row tid>>1, half tid&1
    {
        const int row = tid >> 1, half = tid & 1;
        const uint4* qsrc = (const uint4*)((const char*)(q + ((size_t)b * NS + q0 + row) * NC + h * 64) + half * 64);
        const float* Abp = Ac + b * NC + h * 64 + half * 32;
        const float* Bbp = Bc + b * NC + h * 64 + half * 32;
        char* qdst = smd + row * 144 + half * 64;
#pragma unroll
        for (int i = 0; i < 4; i++) {
            uint4 u = qsrc[i];
            float4 A0 = *(const float4*)(Abp + i * 8);
            float4 A1 = *(const float4*)(Abp + i * 8 + 4);
            float4 B0 = *(const float4*)(Bbp + i * 8);
            float4 B1 = *(const float4*)(Bbp + i * 8 + 4);
            uint16_t* e = (uint16_t*)&u;
            uint4 ov;
            ov.x = packbf(bf2f(e[0]) * A0.x + B0.x, bf2f(e[1]) * A0.y + B0.y);
            ov.y = packbf(bf2f(e[2]) * A0.z + B0.z, bf2f(e[3]) * A0.w + B0.w);
            ov.z = packbf(bf2f(e[4]) * A1.x + B1.x, bf2f(e[5]) * A1.y + B1.y);
            ov.w = packbf(bf2f(e[6]) * A1.z + B1.z, bf2f(e[7]) * A1.w + B1.w);
            *(uint4*)(qdst + i * 16) = ov;
        }
    }
    CP_WAIT1(); __syncthreads();

    uint32_t aq[4][4];
    {
        uint32_t qab = sb + (w * 16 + (lam & 15)) * 144 + (lam >> 4) * 16;
#pragma unroll
        for (int t = 0; t < 4; t++)
            ldm_x4(aq[t][0], aq[t][1], aq[t][2], aq[t][3], qab + t * 32);
    }

    float oacc[8][4];
#pragma unroll
    for (int j = 0; j < 8; j++)
#pragma unroll
        for (int e = 0; e < 4; e++) oacc[j][e] = 0.f;
    float l0 = 0.f, l1 = 0.f;

    const uint32_t kab0 = sb + 18432 + ((lam & 7) + ((lam >> 4) << 3)) * 144
                          + ((lam >> 3) & 1) * 16;
    const uint32_t vab0 = sb + 18432 + 9216 + (lam & 15) * 144 + (lam >> 4) * 16;

    int st = 0;          // stage of current tile i
    for (int i = 0; i < 32; i++) {
        // early prefetch: tile i+2 into free stage (consumed at i-1)
        const int pf = (st + 2 >= 3) ? st - 1 : st + 2;
        if (i + 2 < 32) {
            const char* kgi = kg + (size_t)(i + 2) * kv_step;
            const char* vgi = vg + (size_t)(i + 2) * kv_step;
            uint32_t ko = ksb + pf * 18432, vo = vsb + pf * 18432;
            CP16(ko, kgi); CP16(ko + 16, kgi + 16);
            CP16(vo, vgi); CP16(vo + 16, vgi + 16);
        }
        CP_COMMIT();

        const uint32_t kab = kab0 + st * 18432;
        const uint32_t vab = vab0 + st * 18432;

        // S = Q @ K^T : c[j] covers kv cols 8j..8j+7
        float c[8][4];
#pragma unroll
        for (int j = 0; j < 8; j++)
#pragma unroll
            for (int e = 0; e < 4; e++) c[j][e] = 0.f;
#pragma unroll
        for (int t = 0; t < 4; t++) {
#pragma unroll
            for (int jp = 0; jp < 4; jp++) {
                uint32_t b0, b1, b2, b3;
                ldm_x4(b0, b1, b2, b3, kab + jp * (16 * 144) + t * 32);
                mma_bf16(c[2 * jp],     aq[t], b0, b1);
                mma_bf16(c[2 * jp + 1], aq[t], b2, b3);
            }
        }
        float p0 = 0.f, p1 = 0.f;
#pragma unroll
        for (int j = 0; j < 8; j++) {
            c[j][0] = ex2f(c[j][0]); c[j][1] = ex2f(c[j][1]);
            c[j][2] = ex2f(c[j][2]); c[j][3] = ex2f(c[j][3]);
            p0 += c[j][0] + c[j][1];
            p1 += c[j][2] + c[j][3];
        }
        l0 += p0; l1 += p1;
        uint32_t ap[4][4];
#pragma unroll
        for (int t = 0; t < 4; t++) {
            ap[t][0] = packbf(c[2*t][0],   c[2*t][1]);
            ap[t][1] = packbf(c[2*t][2],   c[2*t][3]);
            ap[t][2] = packbf(c[2*t+1][0], c[2*t+1][1]);
            ap[t][3] = packbf(c[2*t+1][2], c[2*t+1][3]);
        }
#pragma unroll
        for (int t = 0; t < 4; t++) {
#pragma unroll
            for (int jp = 0; jp < 4; jp++) {
                uint32_t b0, b1, b2, b3;
                ldm_x4t(b0, b1, b2, b3, vab + t * (16 * 144) + jp * 32);
                mma_bf16(oacc[2 * jp],     ap[t], b0, b1);
                mma_bf16(oacc[2 * jp + 1], ap[t], b2, b3);
            }
        }
        CP_WAIT1(); __syncthreads();
        st = (st + 1 >= 3) ? 0 : st + 1;
    }

    l0 += __shfl_xor_sync(0xffffffffu, l0, 1);
    l0 += __shfl_xor_sync(0xffffffffu, l0, 2);
    l1 += __shfl_xor_sync(0xffffffffu, l1, 1);
    l1 += __shfl_xor_sync(0xffffffffu, l1, 2);
    const float i0 = 1.f / l0, i1 = 1.f / l1;

    const int r = q0 + w * 16 + (lam >> 2);
    __nv_bfloat16* ob0 = o + ((size_t)b * NS + r) * NC + h * 64 + 2 * (lam & 3);
#pragma unroll
    for (int j = 0; j < 8; j++) {
        *(uint32_t*)(ob0 + j * 8)          = packbf(oacc[j][0] * i0, oacc[j][1] * i0);
        *(uint32_t*)(ob0 + 8 * NC + j * 8) = packbf(oacc[j][2] * i1, oacc[j][3] * i1);
    }
}

// ---------------- launch ----------------
extern "C" void kernel_launch(void* const* d_in, const int* in_sizes, int n_in,
                              void* d_out, int out_size)
{
    const float* hs = (const float*)d_in[0];
    const float* wq = (const float*)d_in[1];
    const float* wk = (const float*)d_in[2];
    const float* wv = (const float*)d_in[3];
    const float* wo = (const float*)d_in[4];
    const float* bo = (const float*)d_in[5];
    float* out = (float*)d_out;

    __nv_bfloat16 *hsb, *wqb, *wkb, *wvb, *wob, *qb, *kbp, *vbp, *obp;
    float *ps, *pq, *Ac, *Bc;
    cudaGetSymbolAddress((void**)&hsb, g_hsb);
    cudaGetSymbolAddress((void**)&wqb, g_wqb);
    cudaGetSymbolAddress((void**)&wkb, g_wkb);
    cudaGetSymbolAddress((void**)&wvb, g_wvb);
    cudaGetSymbolAddress((void**)&wob, g_wob);
    cudaGetSymbolAddress((void**)&qb,  g_qb);
    cudaGetSymbolAddress((void**)&kbp, g_kb);
    cudaGetSymbolAddress((void**)&vbp, g_vb);
    cudaGetSymbolAddress((void**)&obp, g_ob);
    cudaGetSymbolAddress((void**)&ps,  g_ps);
    cudaGetSymbolAddress((void**)&pq,  g_pq);
    cudaGetSymbolAddress((void**)&Ac,  g_A);
    cudaGetSymbolAddress((void**)&Bc,  g_B);

    const int ATTN_SMEM = 18432 + 3 * 18432;   // 73728
    cudaFuncSetAttribute(attn_mma, cudaFuncAttributeMaxDynamicSharedMemorySize, ATTN_SMEM);

    // one merged convert (hs + 4 weights)
    conv_all<<<6720, 256>>>(hs, wq, wk, wv, wo, hsb, wqb, wkb, wvb, wob);

    // merged Q + K + V projections (K/V from source batches 0,2 only)
    // + fused AdaIN stats pass 1 in the Q-path epilogue
    gemm_mma<5><<<dim3(10, 64), 256>>>(hsb, wkb, wvb, wqb, nullptr, nullptr,
                                       nullptr, kbp, vbp, qb, ps, pq);

    // AdaIN stats finalize (warp-parallel) -> affine coeffs
    adain_p2<<<40, 256>>>(ps, pq, Ac, Bc);

    // attention with fused AdaIN-apply on Q
    attn_mma<<<dim3(16, 40), 256, ATTN_SMEM>>>(qb, kbp, vbp, obp, Ac, Bc);

    // output projection + bias + residual (fp32)
    gemm_mma<2><<<dim3(5, 64), 256>>>(obp, wob, nullptr, nullptr, bo, hs,
                                      out, nullptr, nullptr, nullptr, nullptr, nullptr);
}